// round 10
// baseline (speedup 1.0000x reference)
#include <cuda_runtime.h>
#include <cuda_fp16.h>
#include <cstdint>

#define Bq   1024
#define Ssz  20000
#define Spad 20032          // 64 * 313
#define Dsz  256
#define Hh   4
#define SW2  626            // mask words per batch row incl. padded word
#define NCH  9              // split-S chunks
#define TTOT 313            // 64-row s-tiles total

// ---------------- scratch (static device globals; no allocation) ----------------
__device__ float    g_q[Bq * Dsz];
__device__ __half   g_emb_h[(size_t)Spad * 256];         // half emb, zero-padded
__device__ __half   g_wkv_h[512 * 256];                  // half KV weight rows
__device__ __half   g_nc_h[Bq * 256];                    // half neural_context
__device__ __half   g_wq_h[256 * 256];                   // half Q weight rows
__device__ __half   g_wo_h[256 * 256];                   // half out-proj weights
__device__ __half   g_ctx_h[Bq * Dsz];                   // half ctx (out-proj A)
__device__ __half   g_kv[(size_t)Spad * 512];            // [s][0:256]=k, [256:512]=v
__device__ unsigned g_maskT[SW2 * Bq];                   // word-major: [w][b]
__device__ float    g_part[(size_t)NCH * Bq * Dsz];      // [c][b][h*64+d]
__device__ float    g_partl[NCH * Bq * Hh];
__device__ float    g_vpart[400 * Dsz];
__device__ float    g_vmean[Dsz];

// ---------------- helpers --------------------------------------------------------
__device__ __forceinline__ uint32_t smem_u32(const void* p) {
    uint32_t a;
    asm("{ .reg .u64 t; cvta.to.shared.u64 t, %1; cvt.u32.u64 %0, t; }" : "=r"(a) : "l"(p));
    return a;
}
__device__ __forceinline__ uint32_t h2pack(float a, float b) {
    __half2 h = __floats2half2_rn(a, b);
    return *reinterpret_cast<uint32_t*>(&h);
}
__device__ __forceinline__ uint32_t cvt_h2(float lo, float hi) {
    uint32_t r;
    asm("cvt.rn.f16x2.f32 %0, %1, %2;" : "=r"(r) : "f"(hi), "f"(lo));
    return r;
}
__device__ __forceinline__ uint32_t ex2h2(uint32_t x) {
    uint32_t r;
    asm("ex2.approx.f16x2 %0, %1;" : "=r"(r) : "r"(x));
    return r;
}
// swizzled byte offset inside a 64-col (128B-row) half tile; ch = 8-half chunk
__device__ __forceinline__ int toff(int r, int ch) {
    return r * 128 + ((ch ^ (r & 7)) << 4);
}
__device__ __forceinline__ void ldsm_x4(uint32_t& r0, uint32_t& r1, uint32_t& r2,
                                        uint32_t& r3, uint32_t addr) {
    asm volatile("ldmatrix.sync.aligned.m8n8.x4.shared.b16 {%0,%1,%2,%3}, [%4];"
                 : "=r"(r0), "=r"(r1), "=r"(r2), "=r"(r3) : "r"(addr));
}
__device__ __forceinline__ void ldsm_x4_t(uint32_t& r0, uint32_t& r1, uint32_t& r2,
                                          uint32_t& r3, uint32_t addr) {
    asm volatile("ldmatrix.sync.aligned.m8n8.x4.trans.shared.b16 {%0,%1,%2,%3}, [%4];"
                 : "=r"(r0), "=r"(r1), "=r"(r2), "=r"(r3) : "r"(addr));
}
__device__ __forceinline__ void hmma(float* d, uint32_t a0, uint32_t a1, uint32_t a2,
                                     uint32_t a3, uint32_t b0, uint32_t b1) {
    asm volatile(
        "mma.sync.aligned.m16n8k16.row.col.f32.f16.f16.f32 "
        "{%0,%1,%2,%3},{%4,%5,%6,%7},{%8,%9},{%0,%1,%2,%3};"
        : "+f"(d[0]), "+f"(d[1]), "+f"(d[2]), "+f"(d[3])
        : "r"(a0), "r"(a1), "r"(a2), "r"(a3), "r"(b0), "r"(b1));
}
__device__ __forceinline__ void cp_async16(uint32_t dst, const void* src) {
    asm volatile("cp.async.cg.shared.global [%0], [%1], 16;" :: "r"(dst), "l"(src) : "memory");
}
#define CP_COMMIT() asm volatile("cp.async.commit_group;" ::: "memory")
#define CP_WAIT1()  asm volatile("cp.async.wait_group 1;" ::: "memory")

// ---------------- mask bit-packing (transposed; padded word zeroed) --------------
__global__ void pack_mask_kernel(const int* __restrict__ act) {
    int b = blockIdx.x;
    int warp = threadIdx.x >> 5, lane = threadIdx.x & 31;
    for (int w = warp; w < SW2; w += 8) {
        int s = w * 32 + lane;
        int a = (s < Ssz) ? act[(size_t)b * Ssz + s] : 0;
        unsigned m = __ballot_sync(0xFFFFFFFFu, a > 0);
        if (lane == 0) g_maskT[w * Bq + b] = m;
    }
}

// ---------------- fp32 -> fp16 pre-conversion ------------------------------------
#define CROWS (Spad + 512 + Bq + 256 + 256)
__global__ void conv_half(const float* __restrict__ emb, const float* __restrict__ w_in,
                          const float* __restrict__ nc, const float* __restrict__ w_out) {
    int idx = blockIdx.x * 256 + threadIdx.x;
    int r = idx >> 6, c = (idx & 63) * 4;
    if (r < Spad) {
        float4 v = make_float4(0.f, 0.f, 0.f, 0.f);
        if (r < Ssz) v = *(const float4*)(emb + (size_t)r * 256 + c);
        *(uint2*)(g_emb_h + (size_t)r * 256 + c) = make_uint2(h2pack(v.x, v.y), h2pack(v.z, v.w));
    } else if (r < Spad + 512) {
        int rw = r - Spad;
        float4 v = *(const float4*)(w_in + (size_t)(256 + rw) * 256 + c);
        *(uint2*)(g_wkv_h + rw * 256 + c) = make_uint2(h2pack(v.x, v.y), h2pack(v.z, v.w));
    } else if (r < Spad + 512 + Bq) {
        int rn = r - Spad - 512;
        float4 v = *(const float4*)(nc + (size_t)rn * 256 + c);
        *(uint2*)(g_nc_h + rn * 256 + c) = make_uint2(h2pack(v.x, v.y), h2pack(v.z, v.w));
    } else if (r < Spad + 512 + Bq + 256) {
        int rw = r - Spad - 512 - Bq;
        float4 v = *(const float4*)(w_in + (size_t)rw * 256 + c);
        *(uint2*)(g_wq_h + rw * 256 + c) = make_uint2(h2pack(v.x, v.y), h2pack(v.z, v.w));
    } else if (r < CROWS) {
        int rw = r - Spad - 512 - Bq - 256;
        float4 v = *(const float4*)(w_out + (size_t)rw * 256 + c);
        *(uint2*)(g_wo_h + rw * 256 + c) = make_uint2(h2pack(v.x, v.y), h2pack(v.z, v.w));
    }
}

// ---------------- fp16 GEMM, fp32 out: C[1024 x 256] = A_h @ B_h^T + bias --------
#define GH_STG 16384
__global__ __launch_bounds__(256) void gemm_h(const __half* __restrict__ Ah,
                                              const __half* __restrict__ Bh,
                                              const float* __restrict__ bias,
                                              float* __restrict__ C) {
    extern __shared__ __align__(16) char sm[];
    const uint32_t sb = smem_u32(sm);
    const int t = threadIdx.x, w = t >> 5, lane = t & 31;
    const int m0 = blockIdx.y * 64, n0 = blockIdx.x * 64;
    const int mw_ = (w >> 1) * 16, nw_ = (w & 1) * 32;
    const int qr = lane >> 2, tg = lane & 3;
    const int aL4 = (lane >> 4) & 1, bL3 = (lane >> 3) & 1;
    const int ar = mw_ + (lane & 7) + (lane & 8), ar7 = ar & 7;
    const int br = nw_ + (lane & 7) + aL4 * 8, br7 = br & 7;
    const int pr = t >> 3, pch = t & 7;
#pragma unroll
    for (int pf = 0; pf < 2; pf++) {
        uint32_t base = sb + pf * GH_STG;
#pragma unroll
        for (int i = 0; i < 2; i++) {
            int r = pr + i * 32;
            cp_async16(base + toff(r, pch), Ah + (size_t)(m0 + r) * 256 + pf * 64 + pch * 8);
            cp_async16(base + 8192 + toff(r, pch), Bh + (n0 + r) * 256 + pf * 64 + pch * 8);
        }
        CP_COMMIT();
    }
    float acc[4][4] = {};
    for (int k0 = 0; k0 < 4; k0++) {
        const uint32_t ab = sb + (k0 % 3) * GH_STG, bb_ = ab + 8192;
        CP_WAIT1();
        __syncthreads();
        {
            int kp = k0 + 2;
            if (kp < 4) {
                uint32_t base = sb + (kp % 3) * GH_STG;
#pragma unroll
                for (int i = 0; i < 2; i++) {
                    int r = pr + i * 32;
                    cp_async16(base + toff(r, pch), Ah + (size_t)(m0 + r) * 256 + kp * 64 + pch * 8);
                    cp_async16(base + 8192 + toff(r, pch), Bh + (n0 + r) * 256 + kp * 64 + pch * 8);
                }
            }
            CP_COMMIT();
        }
#pragma unroll
        for (int kk = 0; kk < 64; kk += 16) {
            int c8 = kk >> 3;
            uint32_t a0, a1, a2, a3, b0, b1, b2, b3, c0, c1, c2, c3;
            ldsm_x4(a0, a1, a2, a3, ab + ar * 128 + (((c8 + aL4) ^ ar7) << 4));
            ldsm_x4(b0, b1, b2, b3, bb_ + br * 128 + (((c8 + bL3) ^ br7) << 4));
            hmma(acc[0], a0, a1, a2, a3, b0, b1);
            hmma(acc[1], a0, a1, a2, a3, b2, b3);
            ldsm_x4(c0, c1, c2, c3, bb_ + (br + 16) * 128 + (((c8 + bL3) ^ br7) << 4));
            hmma(acc[2], a0, a1, a2, a3, c0, c1);
            hmma(acc[3], a0, a1, a2, a3, c2, c3);
        }
    }
    const int r0 = m0 + mw_ + qr, r1 = r0 + 8;
#pragma unroll
    for (int nt = 0; nt < 4; nt++) {
        int col = n0 + nw_ + nt * 8 + tg * 2;
        float bx = bias[col], by = bias[col + 1];
        *(float2*)(C + (size_t)r0 * 256 + col) = make_float2(acc[nt][0] + bx, acc[nt][1] + by);
        *(float2*)(C + (size_t)r1 * 256 + col) = make_float2(acc[nt][2] + bx, acc[nt][3] + by);
    }
}

// ---------------- KV projection: fp16 mma + cp.async 3-stage pipeline ------------
#define KV_STG 16384
__global__ __launch_bounds__(256) void gemm_kv_p(const float* __restrict__ bias,
                                                 __half* __restrict__ C) {
    extern __shared__ __align__(16) char sm[];
    const uint32_t sb = smem_u32(sm);
    const int t = threadIdx.x, w = t >> 5, lane = t & 31;
    const int m0 = blockIdx.y * 64, n0 = blockIdx.x * 64;
    const int mw_ = (w >> 1) * 16, nw_ = (w & 1) * 32;
    const int qr = lane >> 2, tg = lane & 3;
    const int aL4 = (lane >> 4) & 1, bL3 = (lane >> 3) & 1;
    const int ar = mw_ + (lane & 7) + (lane & 8), ar7 = ar & 7;
    const int br = nw_ + (lane & 7) + aL4 * 8, br7 = br & 7;
    const int pr = t >> 3, pch = t & 7;
#pragma unroll
    for (int pf = 0; pf < 2; pf++) {
        uint32_t base = sb + pf * KV_STG;
#pragma unroll
        for (int i = 0; i < 2; i++) {
            int r = pr + i * 32;
            cp_async16(base + toff(r, pch),
                       g_emb_h + (size_t)(m0 + r) * 256 + pf * 64 + pch * 8);
            cp_async16(base + 8192 + toff(r, pch),
                       g_wkv_h + (n0 + r) * 256 + pf * 64 + pch * 8);
        }
        CP_COMMIT();
    }
    float acc[4][4] = {};
    for (int k0 = 0; k0 < 4; k0++) {
        const uint32_t ab = sb + (k0 % 3) * KV_STG, bb_ = ab + 8192;
        CP_WAIT1();
        __syncthreads();
        {
            int kp = k0 + 2;
            if (kp < 4) {
                uint32_t base = sb + (kp % 3) * KV_STG;
#pragma unroll
                for (int i = 0; i < 2; i++) {
                    int r = pr + i * 32;
                    cp_async16(base + toff(r, pch),
                               g_emb_h + (size_t)(m0 + r) * 256 + kp * 64 + pch * 8);
                    cp_async16(base + 8192 + toff(r, pch),
                               g_wkv_h + (n0 + r) * 256 + kp * 64 + pch * 8);
                }
            }
            CP_COMMIT();
        }
#pragma unroll
        for (int kk = 0; kk < 64; kk += 16) {
            int c8 = kk >> 3;
            uint32_t a0, a1, a2, a3, b0, b1, b2, b3, c0, c1, c2, c3;
            ldsm_x4(a0, a1, a2, a3, ab + ar * 128 + (((c8 + aL4) ^ ar7) << 4));
            ldsm_x4(b0, b1, b2, b3, bb_ + br * 128 + (((c8 + bL3) ^ br7) << 4));
            hmma(acc[0], a0, a1, a2, a3, b0, b1);
            hmma(acc[1], a0, a1, a2, a3, b2, b3);
            ldsm_x4(c0, c1, c2, c3, bb_ + (br + 16) * 128 + (((c8 + bL3) ^ br7) << 4));
            hmma(acc[2], a0, a1, a2, a3, c0, c1);
            hmma(acc[3], a0, a1, a2, a3, c2, c3);
        }
    }
    const int r0 = m0 + mw_ + qr, r1 = r0 + 8;
#pragma unroll
    for (int nt = 0; nt < 4; nt++) {
        int col = n0 + nw_ + nt * 8 + tg * 2;
        float bx = bias[col], by = bias[col + 1];
        *(__half2*)(C + (size_t)r0 * 512 + col) = __floats2half2_rn(acc[nt][0] + bx, acc[nt][1] + by);
        *(__half2*)(C + (size_t)r1 * 512 + col) = __floats2half2_rn(acc[nt][2] + bx, acc[nt][3] + by);
    }
}

// ---------------- v_mean (2-stage, deterministic, 2-way ILP) ---------------------
__global__ void vmean1_kernel() {
    int c = blockIdx.x, d = threadIdx.x;
    float s0 = 0.f, s1 = 0.f;
#pragma unroll 5
    for (int i = 0; i < 50; i += 2) {
        s0 += __half2float(g_kv[(size_t)(c * 50 + i) * 512 + 256 + d]);
        s1 += __half2float(g_kv[(size_t)(c * 50 + i + 1) * 512 + 256 + d]);
    }
    g_vpart[c * Dsz + d] = s0 + s1;
}
__global__ void vmean2_kernel() {
    int d = threadIdx.x;
    float s = 0.f;
    for (int c = 0; c < 400; c++) s += g_vpart[c * Dsz + d];
    g_vmean[d] = s * (1.0f / (float)Ssz);
}

// ---------------- split-S attention: M32 warp tiles, 128-row CTA -----------------
// Warp w: rows (w>>1)*32..+31, s-half (w&1)*32. QK M32xN32xk64, PV M32xN64xk32.
// ctxs/lsm aliased over dead K/V stage buffers after the loop (barrier-protected).
#define A3_Q   0            // 16 KB: 128 rows x 128B
#define A3_K   16384        // 3 x 8 KB K stages
#define A3_V   40960        // 3 x 8 KB V stages
#define A3_CT  16384        // alias: 128x64 fp32 = 32 KB
#define A3_LS  49152        // alias: 256 floats
#define SM_AT3 65536
#define ONES2 0x3C003C00u

__global__ __launch_bounds__(256, 1) void attn_h3() {
    extern __shared__ __align__(16) char sm[];
    const uint32_t sb = smem_u32(sm);
    const uint32_t qb = sb + A3_Q;
    float* ctxs = (float*)(sm + A3_CT);
    float* lsm  = (float*)(sm + A3_LS);
    const int t = threadIdx.x, w = t >> 5, lane = t & 31;
    const int c = blockIdx.x, bt = blockIdx.y, h = blockIdx.z;
    const int mw_ = (w >> 1) * 32, sh = w & 1;
    const int qr = lane >> 2, tg = lane & 3;
    const int aL4 = (lane >> 4) & 1, bL3 = (lane >> 3) & 1;
    const int ar = mw_ + (lane & 7) + (lane & 8), ar7 = ar & 7;
    const int br = sh * 32 + (lane & 7) + aL4 * 8, br7 = br & 7;
    const int vl7 = lane & 7;

    { // Q tile: 128 rows, fp32 -> half, scale = (1/8)*log2(e)
        const float QS = 0.125f * 1.44269504f;
        char* qc = sm + A3_Q;
#pragma unroll
        for (int i = 0; i < 4; i++) {
            int idx = t + i * 256;
            int r = idx >> 3, ch = idx & 7;
            const float* qp = g_q + (size_t)(bt * 128 + r) * 256 + h * 64 + ch * 8;
            float4 x = *(const float4*)qp, y = *(const float4*)(qp + 4);
            *(uint4*)(qc + toff(r, ch)) =
                make_uint4(h2pack(x.x * QS, x.y * QS), h2pack(x.z * QS, x.w * QS),
                           h2pack(y.x * QS, y.y * QS), h2pack(y.z * QS, y.w * QS));
        }
    }
    const int t0 = (TTOT * c) / NCH, t1 = (TTOT * (c + 1)) / NCH;
    const int pr = t >> 3, pch = t & 7;
#pragma unroll
    for (int pf = 0; pf < 2; pf++) {
        int ts = t0 + pf;
        if (ts < t1) {
            uint32_t kd = sb + A3_K + pf * 8192, vd = sb + A3_V + pf * 8192;
#pragma unroll
            for (int i = 0; i < 2; i++) {
                int r = pr + i * 32;
                const __half* kp = g_kv + (size_t)(ts * 64 + r) * 512 + h * 64 + pch * 8;
                cp_async16(kd + toff(r, pch), kp);
                cp_async16(vd + toff(r, pch), kp + 256);
            }
        }
        CP_COMMIT();
    }
    __syncthreads();          // Q tile visible
    // hoist Q A-fragments for both 16-row halves
    uint32_t qa[4][8];
#pragma unroll
    for (int kq = 0; kq < 4; kq++) {
        uint32_t xo = (((kq * 2) + aL4) ^ ar7) << 4;
        ldsm_x4(qa[kq][0], qa[kq][1], qa[kq][2], qa[kq][3], qb + ar * 128 + xo);
        ldsm_x4(qa[kq][4], qa[kq][5], qa[kq][6], qa[kq][7], qb + (ar + 16) * 128 + xo);
    }

    float ctx[2][8][4] = {};
    float lacc[2][4] = {};

    for (int ts = t0; ts < t1; ts++) {
        const int st = (ts - t0) % 3;
        const uint32_t kb = sb + A3_K + st * 8192;
        const uint32_t vb = sb + A3_V + st * 8192;
        CP_WAIT1();
        __syncthreads();
        { // prefetch ts+2
            int tp = ts + 2;
            if (tp < t1) {
                int sp = (ts - t0 + 2) % 3;
                uint32_t kd = sb + A3_K + sp * 8192, vd = sb + A3_V + sp * 8192;
#pragma unroll
                for (int i = 0; i < 2; i++) {
                    int r = pr + i * 32;
                    const __half* kp = g_kv + (size_t)(tp * 64 + r) * 512 + h * 64 + pch * 8;
                    cp_async16(kd + toff(r, pch), kp);
                    cp_async16(vd + toff(r, pch), kp + 256);
                }
            }
            CP_COMMIT();
        }
        const size_t mbase = (size_t)(2 * ts + sh) * Bq + bt * 128 + mw_;
        unsigned mwr[2][2];
        mwr[0][0] = g_maskT[mbase + qr];      mwr[0][1] = g_maskT[mbase + qr + 8];
        mwr[1][0] = g_maskT[mbase + qr + 16]; mwr[1][1] = g_maskT[mbase + qr + 24];
        // ---- scores(log2) = Q' @ K^T : M32 x N32 x k64 ----
        float scf[2][4][4] = {};
#pragma unroll
        for (int kk = 0; kk < 64; kk += 16) {
            int c8 = kk >> 3, kq = kk >> 4;
            uint32_t b0, b1, b2, b3, c0, c1, c2, c3;
            ldsm_x4(b0, b1, b2, b3, kb + br * 128 + (((c8 + bL3) ^ br7) << 4));
            ldsm_x4(c0, c1, c2, c3, kb + (br + 16) * 128 + (((c8 + bL3) ^ br7) << 4));
#pragma unroll
            for (int rh = 0; rh < 2; rh++) {
                uint32_t A0 = qa[kq][rh * 4], A1 = qa[kq][rh * 4 + 1],
                         A2 = qa[kq][rh * 4 + 2], A3 = qa[kq][rh * 4 + 3];
                hmma(scf[rh][0], A0, A1, A2, A3, b0, b1);
                hmma(scf[rh][1], A0, A1, A2, A3, b2, b3);
                hmma(scf[rh][2], A0, A1, A2, A3, c0, c1);
                hmma(scf[rh][3], A0, A1, A2, A3, c2, c3);
            }
        }
        // ---- p = 2^score via ex2.f16x2, mask by AND; l-sum via HMMA-ones ----
        uint32_t pa[2][2][4];
#pragma unroll
        for (int rh = 0; rh < 2; rh++) {
#pragma unroll
            for (int ks2 = 0; ks2 < 2; ks2++) {
#pragma unroll
                for (int q2 = 0; q2 < 2; q2++) {
                    int nt = 2 * ks2 + q2;
                    int bp = nt * 8 + tg * 2;
                    uint32_t am0 = (((mwr[rh][0] >> bp) & 1u) ? 0x0000FFFFu : 0u) |
                                   (((mwr[rh][0] >> (bp + 1)) & 1u) ? 0xFFFF0000u : 0u);
                    uint32_t am1 = (((mwr[rh][1] >> bp) & 1u) ? 0x0000FFFFu : 0u) |
                                   (((mwr[rh][1] >> (bp + 1)) & 1u) ? 0xFFFF0000u : 0u);
                    pa[rh][ks2][2 * q2]     = ex2h2(cvt_h2(scf[rh][nt][0], scf[rh][nt][1])) & am0;
                    pa[rh][ks2][2 * q2 + 1] = ex2h2(cvt_h2(scf[rh][nt][2], scf[rh][nt][3])) & am1;
                }
                hmma(lacc[rh], pa[rh][ks2][0], pa[rh][ks2][1], pa[rh][ks2][2], pa[rh][ks2][3],
                     ONES2, ONES2);
            }
        }
        // ---- ctx += P @ V : M32 x N64 x k32, B via ldmatrix.trans ----
#pragma unroll
        for (int ks2 = 0; ks2 < 2; ks2++) {
            int vrow = sh * 32 + ks2 * 16 + vl7 + bL3 * 8;
#pragma unroll
            for (int j = 0; j < 4; j++) {
                uint32_t b0, b1, b2, b3;
                ldsm_x4_t(b0, b1, b2, b3, vb + vrow * 128 + ((((j << 1) + aL4) ^ vl7) << 4));
#pragma unroll
                for (int rh = 0; rh < 2; rh++) {
                    hmma(ctx[rh][2 * j],     pa[rh][ks2][0], pa[rh][ks2][1],
                         pa[rh][ks2][2], pa[rh][ks2][3], b0, b1);
                    hmma(ctx[rh][2 * j + 1], pa[rh][ks2][0], pa[rh][ks2][1],
                         pa[rh][ks2][2], pa[rh][ks2][3], b2, b3);
                }
            }
        }
    }
    __syncthreads();          // all V reads done before aliasing ctxs/lsm over stages
    if (sh == 1) {
#pragma unroll
        for (int rh = 0; rh < 2; rh++) {
            int r0 = mw_ + rh * 16 + qr, r1 = r0 + 8;
#pragma unroll
            for (int nc = 0; nc < 8; nc++) {
                *(float2*)&ctxs[r0 * 64 + nc * 8 + tg * 2] =
                    make_float2(ctx[rh][nc][0], ctx[rh][nc][1]);
                *(float2*)&ctxs[r1 * 64 + nc * 8 + tg * 2] =
                    make_float2(ctx[rh][nc][2], ctx[rh][nc][3]);
            }
        }
    }
    if (tg == 0) {
#pragma unroll
        for (int rh = 0; rh < 2; rh++) {
            lsm[sh * 128 + mw_ + rh * 16 + qr]     = lacc[rh][0];
            lsm[sh * 128 + mw_ + rh * 16 + qr + 8] = lacc[rh][2];
        }
    }
    __syncthreads();
    if (sh == 0) {
        size_t base = ((size_t)c * Bq + bt * 128) * Dsz + (size_t)h * 64;
#pragma unroll
        for (int rh = 0; rh < 2; rh++) {
            int r0 = mw_ + rh * 16 + qr, r1 = r0 + 8;
#pragma unroll
            for (int nc = 0; nc < 8; nc++) {
                int col = nc * 8 + tg * 2;
                float2 o0 = *(float2*)&ctxs[r0 * 64 + col];
                float2 o1 = *(float2*)&ctxs[r1 * 64 + col];
                *(float2*)(g_part + base + (size_t)r0 * Dsz + col) =
                    make_float2(ctx[rh][nc][0] + o0.x, ctx[rh][nc][1] + o0.y);
                *(float2*)(g_part + base + (size_t)r1 * Dsz + col) =
                    make_float2(ctx[rh][nc][2] + o1.x, ctx[rh][nc][3] + o1.y);
            }
        }
    }
    if (t < 128)
        g_partl[((size_t)c * Bq + bt * 128 + t) * Hh + h] = lsm[t] + lsm[128 + t];
}

// ---------------- merge partials, normalize (half ctx out) -----------------------
__global__ void reduce_ctx_kernel() {
    int b = blockIdx.x, d = threadIdx.x;
    int h = d >> 6;
    float l = 0.f, s = 0.f;
    for (int c = 0; c < NCH; c++) {
        l += g_partl[((size_t)c * Bq + b) * Hh + h];
        s += g_part[((size_t)c * Bq + b) * Dsz + d];
    }
    float v = (l > 0.f) ? (s / l) : g_vmean[d];
    g_ctx_h[b * Dsz + d] = __float2half_rn(v);
}

// ---------------- launch ---------------------------------------------------------
extern "C" void kernel_launch(void* const* d_in, const int* in_sizes, int n_in,
                              void* d_out, int out_size) {
    const int*   act   = (const int*)d_in[0];
    const float* nc    = (const float*)d_in[1];
    const float* emb   = (const float*)d_in[2];
    const float* w_in  = (const float*)d_in[3];
    const float* b_in  = (const float*)d_in[4];
    const float* w_out = (const float*)d_in[5];
    const float* b_out = (const float*)d_in[6];
    float* out = (float*)d_out;
    (void)in_sizes; (void)n_in; (void)out_size;

    void *p_kv = 0, *p_q = 0;
    void *p_nc = 0, *p_wq = 0, *p_wo = 0, *p_ctx = 0;
    cudaGetSymbolAddress(&p_kv, g_kv);
    cudaGetSymbolAddress(&p_q, g_q);
    cudaGetSymbolAddress(&p_nc, g_nc_h);
    cudaGetSymbolAddress(&p_wq, g_wq_h);
    cudaGetSymbolAddress(&p_wo, g_wo_h);
    cudaGetSymbolAddress(&p_ctx, g_ctx_h);

    cudaFuncSetAttribute(attn_h3, cudaFuncAttributeMaxDynamicSharedMemorySize, SM_AT3);
    cudaFuncSetAttribute(gemm_kv_p, cudaFuncAttributeMaxDynamicSharedMemorySize, 3 * KV_STG);
    cudaFuncSetAttribute(gemm_h, cudaFuncAttributeMaxDynamicSharedMemorySize, 3 * GH_STG);

    pack_mask_kernel<<<Bq, 256>>>(act);
    conv_half<<<CROWS / 4, 256>>>(emb, w_in, nc, w_out);
    gemm_kv_p<<<dim3(8, Spad / 64), 256, 3 * KV_STG>>>(b_in + 256, (__half*)p_kv);
    gemm_h<<<dim3(4, 16), 256, 3 * GH_STG>>>((const __half*)p_nc, (const __half*)p_wq,
                                             b_in, (float*)p_q);
    vmean1_kernel<<<400, 256>>>();
    vmean2_kernel<<<1, 256>>>();
    attn_h3<<<dim3(NCH, Bq / 128, Hh), 256, SM_AT3>>>();
    reduce_ctx_kernel<<<Bq, 256>>>();
    gemm_h<<<dim3(4, 16), 256, 3 * GH_STG>>>((const __half*)p_ctx, (const __half*)p_wo,
                                             b_out, out);
}

// round 12
// speedup vs baseline: 1.0419x; 1.0419x over previous
#include <cuda_runtime.h>
#include <cuda_fp16.h>
#include <cstdint>

#define Bq   1024
#define Ssz  20000
#define Spad 20032          // 64 * 313
#define Dsz  256
#define Hh   4
#define SW2  626            // mask words per batch row incl. padded word
#define NCH  9              // split-S chunks
#define TTOT 313            // 64-row s-tiles total

// ---------------- scratch (static device globals; no allocation) ----------------
__device__ float    g_q[Bq * Dsz];
__device__ __half   g_emb_h[(size_t)Spad * 256];         // half emb, zero-padded
__device__ __half   g_wkv_h[512 * 256];                  // half KV weight rows
__device__ __half   g_nc_h[Bq * 256];                    // half neural_context
__device__ __half   g_wq_h[256 * 256];                   // half Q weight rows
__device__ __half   g_wo_h[256 * 256];                   // half out-proj weights
__device__ __half   g_ctx_h[Bq * Dsz];                   // half ctx (out-proj A)
__device__ __half   g_kv[(size_t)Spad * 512];            // [s][0:256]=k, [256:512]=v
__device__ unsigned g_maskT[SW2 * Bq];                   // word-major: [w][b]
__device__ float    g_part[(size_t)NCH * Bq * Dsz];      // [c][b][h*64+d]
__device__ float    g_partl[NCH * Bq * Hh];
__device__ float    g_vpart[800 * Dsz];
__device__ float    g_vmean[Dsz];

// ---------------- helpers --------------------------------------------------------
__device__ __forceinline__ uint32_t smem_u32(const void* p) {
    uint32_t a;
    asm("{ .reg .u64 t; cvta.to.shared.u64 t, %1; cvt.u32.u64 %0, t; }" : "=r"(a) : "l"(p));
    return a;
}
__device__ __forceinline__ uint32_t h2pack(float a, float b) {
    __half2 h = __floats2half2_rn(a, b);
    return *reinterpret_cast<uint32_t*>(&h);
}
__device__ __forceinline__ uint32_t cvt_h2(float lo, float hi) {
    uint32_t r;
    asm("cvt.rn.f16x2.f32 %0, %1, %2;" : "=r"(r) : "f"(hi), "f"(lo));
    return r;
}
__device__ __forceinline__ uint32_t ex2h2(uint32_t x) {
    uint32_t r;
    asm("ex2.approx.f16x2 %0, %1;" : "=r"(r) : "r"(x));
    return r;
}
// swizzled byte offset inside a 64-col (128B-row) half tile; ch = 8-half chunk
__device__ __forceinline__ int toff(int r, int ch) {
    return r * 128 + ((ch ^ (r & 7)) << 4);
}
__device__ __forceinline__ void ldsm_x4(uint32_t& r0, uint32_t& r1, uint32_t& r2,
                                        uint32_t& r3, uint32_t addr) {
    asm volatile("ldmatrix.sync.aligned.m8n8.x4.shared.b16 {%0,%1,%2,%3}, [%4];"
                 : "=r"(r0), "=r"(r1), "=r"(r2), "=r"(r3) : "r"(addr));
}
__device__ __forceinline__ void ldsm_x4_t(uint32_t& r0, uint32_t& r1, uint32_t& r2,
                                          uint32_t& r3, uint32_t addr) {
    asm volatile("ldmatrix.sync.aligned.m8n8.x4.trans.shared.b16 {%0,%1,%2,%3}, [%4];"
                 : "=r"(r0), "=r"(r1), "=r"(r2), "=r"(r3) : "r"(addr));
}
__device__ __forceinline__ void hmma(float* d, uint32_t a0, uint32_t a1, uint32_t a2,
                                     uint32_t a3, uint32_t b0, uint32_t b1) {
    asm volatile(
        "mma.sync.aligned.m16n8k16.row.col.f32.f16.f16.f32 "
        "{%0,%1,%2,%3},{%4,%5,%6,%7},{%8,%9},{%0,%1,%2,%3};"
        : "+f"(d[0]), "+f"(d[1]), "+f"(d[2]), "+f"(d[3])
        : "r"(a0), "r"(a1), "r"(a2), "r"(a3), "r"(b0), "r"(b1));
}
__device__ __forceinline__ void cp_async16(uint32_t dst, const void* src) {
    asm volatile("cp.async.cg.shared.global [%0], [%1], 16;" :: "r"(dst), "l"(src) : "memory");
}
#define CP_COMMIT() asm volatile("cp.async.commit_group;" ::: "memory")
#define CP_WAIT1()  asm volatile("cp.async.wait_group 1;" ::: "memory")

// ---------------- mask bit-packing: int4 loads + nibble assembly -----------------
__global__ void pack_mask_kernel(const int* __restrict__ act) {
    __shared__ unsigned char nib[256];
    const int b = blockIdx.x, t = threadIdx.x;
    const int* row = act + (size_t)b * Ssz;
    for (int it = 0; it < 20; it++) {
        int s = it * 1024 + t * 4;
        unsigned n = 0;
        if (s + 3 < Ssz) {
            int4 a = *(const int4*)(row + s);
            n = (unsigned)(a.x > 0) | ((unsigned)(a.y > 0) << 1) |
                ((unsigned)(a.z > 0) << 2) | ((unsigned)(a.w > 0) << 3);
        } else {
#pragma unroll
            for (int j = 0; j < 4; j++) {
                int ss = s + j;
                if (ss < Ssz && row[ss] > 0) n |= 1u << j;
            }
        }
        nib[t] = (unsigned char)n;
        __syncthreads();
        if (t < 32) {
            int w = it * 32 + t;
            if (w < SW2) {
                uint2 v = *(const uint2*)(nib + t * 8);
                unsigned lo = v.x, hi = v.y;
                unsigned word = (lo & 0xFu) | (((lo >> 8) & 0xFu) << 4) |
                                (((lo >> 16) & 0xFu) << 8) | (((lo >> 24) & 0xFu) << 12) |
                                ((hi & 0xFu) << 16) | (((hi >> 8) & 0xFu) << 20) |
                                (((hi >> 16) & 0xFu) << 24) | (((hi >> 24) & 0xFu) << 28);
                g_maskT[w * Bq + b] = word;
            }
        }
        __syncthreads();
    }
}

// ---------------- fp32 -> fp16 pre-conversion ------------------------------------
#define CROWS (Spad + 512 + Bq + 256 + 256)
__global__ void conv_half(const float* __restrict__ emb, const float* __restrict__ w_in,
                          const float* __restrict__ nc, const float* __restrict__ w_out) {
    int idx = blockIdx.x * 256 + threadIdx.x;
    int r = idx >> 6, c = (idx & 63) * 4;
    if (r < Spad) {
        float4 v = make_float4(0.f, 0.f, 0.f, 0.f);
        if (r < Ssz) v = *(const float4*)(emb + (size_t)r * 256 + c);
        *(uint2*)(g_emb_h + (size_t)r * 256 + c) = make_uint2(h2pack(v.x, v.y), h2pack(v.z, v.w));
    } else if (r < Spad + 512) {
        int rw = r - Spad;
        float4 v = *(const float4*)(w_in + (size_t)(256 + rw) * 256 + c);
        *(uint2*)(g_wkv_h + rw * 256 + c) = make_uint2(h2pack(v.x, v.y), h2pack(v.z, v.w));
    } else if (r < Spad + 512 + Bq) {
        int rn = r - Spad - 512;
        float4 v = *(const float4*)(nc + (size_t)rn * 256 + c);
        *(uint2*)(g_nc_h + rn * 256 + c) = make_uint2(h2pack(v.x, v.y), h2pack(v.z, v.w));
    } else if (r < Spad + 512 + Bq + 256) {
        int rw = r - Spad - 512 - Bq;
        float4 v = *(const float4*)(w_in + (size_t)rw * 256 + c);
        *(uint2*)(g_wq_h + rw * 256 + c) = make_uint2(h2pack(v.x, v.y), h2pack(v.z, v.w));
    } else if (r < CROWS) {
        int rw = r - Spad - 512 - Bq - 256;
        float4 v = *(const float4*)(w_out + (size_t)rw * 256 + c);
        *(uint2*)(g_wo_h + rw * 256 + c) = make_uint2(h2pack(v.x, v.y), h2pack(v.z, v.w));
    }
}

// ---------------- fp16 GEMM, fp32 out: C[1024 x 256] = A_h @ B_h^T + bias --------
#define GH_STG 16384
__global__ __launch_bounds__(256) void gemm_h(const __half* __restrict__ Ah,
                                              const __half* __restrict__ Bh,
                                              const float* __restrict__ bias,
                                              float* __restrict__ C) {
    extern __shared__ __align__(16) char sm[];
    const uint32_t sb = smem_u32(sm);
    const int t = threadIdx.x, w = t >> 5, lane = t & 31;
    const int m0 = blockIdx.y * 64, n0 = blockIdx.x * 64;
    const int mw_ = (w >> 1) * 16, nw_ = (w & 1) * 32;
    const int qr = lane >> 2, tg = lane & 3;
    const int aL4 = (lane >> 4) & 1, bL3 = (lane >> 3) & 1;
    const int ar = mw_ + (lane & 7) + (lane & 8), ar7 = ar & 7;
    const int br = nw_ + (lane & 7) + aL4 * 8, br7 = br & 7;
    const int pr = t >> 3, pch = t & 7;
#pragma unroll
    for (int pf = 0; pf < 2; pf++) {
        uint32_t base = sb + pf * GH_STG;
#pragma unroll
        for (int i = 0; i < 2; i++) {
            int r = pr + i * 32;
            cp_async16(base + toff(r, pch), Ah + (size_t)(m0 + r) * 256 + pf * 64 + pch * 8);
            cp_async16(base + 8192 + toff(r, pch), Bh + (n0 + r) * 256 + pf * 64 + pch * 8);
        }
        CP_COMMIT();
    }
    float acc[4][4] = {};
    for (int k0 = 0; k0 < 4; k0++) {
        const uint32_t ab = sb + (k0 % 3) * GH_STG, bb_ = ab + 8192;
        CP_WAIT1();
        __syncthreads();
        {
            int kp = k0 + 2;
            if (kp < 4) {
                uint32_t base = sb + (kp % 3) * GH_STG;
#pragma unroll
                for (int i = 0; i < 2; i++) {
                    int r = pr + i * 32;
                    cp_async16(base + toff(r, pch), Ah + (size_t)(m0 + r) * 256 + kp * 64 + pch * 8);
                    cp_async16(base + 8192 + toff(r, pch), Bh + (n0 + r) * 256 + kp * 64 + pch * 8);
                }
            }
            CP_COMMIT();
        }
#pragma unroll
        for (int kk = 0; kk < 64; kk += 16) {
            int c8 = kk >> 3;
            uint32_t a0, a1, a2, a3, b0, b1, b2, b3, c0, c1, c2, c3;
            ldsm_x4(a0, a1, a2, a3, ab + ar * 128 + (((c8 + aL4) ^ ar7) << 4));
            ldsm_x4(b0, b1, b2, b3, bb_ + br * 128 + (((c8 + bL3) ^ br7) << 4));
            hmma(acc[0], a0, a1, a2, a3, b0, b1);
            hmma(acc[1], a0, a1, a2, a3, b2, b3);
            ldsm_x4(c0, c1, c2, c3, bb_ + (br + 16) * 128 + (((c8 + bL3) ^ br7) << 4));
            hmma(acc[2], a0, a1, a2, a3, c0, c1);
            hmma(acc[3], a0, a1, a2, a3, c2, c3);
        }
    }
    const int r0 = m0 + mw_ + qr, r1 = r0 + 8;
#pragma unroll
    for (int nt = 0; nt < 4; nt++) {
        int col = n0 + nw_ + nt * 8 + tg * 2;
        float bx = bias[col], by = bias[col + 1];
        *(float2*)(C + (size_t)r0 * 256 + col) = make_float2(acc[nt][0] + bx, acc[nt][1] + by);
        *(float2*)(C + (size_t)r1 * 256 + col) = make_float2(acc[nt][2] + bx, acc[nt][3] + by);
    }
}

// ---------------- KV projection: fp16 mma + cp.async 3-stage pipeline ------------
#define KV_STG 16384
__global__ __launch_bounds__(256) void gemm_kv_p(const float* __restrict__ bias,
                                                 __half* __restrict__ C) {
    extern __shared__ __align__(16) char sm[];
    const uint32_t sb = smem_u32(sm);
    const int t = threadIdx.x, w = t >> 5, lane = t & 31;
    const int m0 = blockIdx.y * 64, n0 = blockIdx.x * 64;
    const int mw_ = (w >> 1) * 16, nw_ = (w & 1) * 32;
    const int qr = lane >> 2, tg = lane & 3;
    const int aL4 = (lane >> 4) & 1, bL3 = (lane >> 3) & 1;
    const int ar = mw_ + (lane & 7) + (lane & 8), ar7 = ar & 7;
    const int br = nw_ + (lane & 7) + aL4 * 8, br7 = br & 7;
    const int pr = t >> 3, pch = t & 7;
#pragma unroll
    for (int pf = 0; pf < 2; pf++) {
        uint32_t base = sb + pf * KV_STG;
#pragma unroll
        for (int i = 0; i < 2; i++) {
            int r = pr + i * 32;
            cp_async16(base + toff(r, pch),
                       g_emb_h + (size_t)(m0 + r) * 256 + pf * 64 + pch * 8);
            cp_async16(base + 8192 + toff(r, pch),
                       g_wkv_h + (n0 + r) * 256 + pf * 64 + pch * 8);
        }
        CP_COMMIT();
    }
    float acc[4][4] = {};
    for (int k0 = 0; k0 < 4; k0++) {
        const uint32_t ab = sb + (k0 % 3) * KV_STG, bb_ = ab + 8192;
        CP_WAIT1();
        __syncthreads();
        {
            int kp = k0 + 2;
            if (kp < 4) {
                uint32_t base = sb + (kp % 3) * KV_STG;
#pragma unroll
                for (int i = 0; i < 2; i++) {
                    int r = pr + i * 32;
                    cp_async16(base + toff(r, pch),
                               g_emb_h + (size_t)(m0 + r) * 256 + kp * 64 + pch * 8);
                    cp_async16(base + 8192 + toff(r, pch),
                               g_wkv_h + (n0 + r) * 256 + kp * 64 + pch * 8);
                }
            }
            CP_COMMIT();
        }
#pragma unroll
        for (int kk = 0; kk < 64; kk += 16) {
            int c8 = kk >> 3;
            uint32_t a0, a1, a2, a3, b0, b1, b2, b3, c0, c1, c2, c3;
            ldsm_x4(a0, a1, a2, a3, ab + ar * 128 + (((c8 + aL4) ^ ar7) << 4));
            ldsm_x4(b0, b1, b2, b3, bb_ + br * 128 + (((c8 + bL3) ^ br7) << 4));
            hmma(acc[0], a0, a1, a2, a3, b0, b1);
            hmma(acc[1], a0, a1, a2, a3, b2, b3);
            ldsm_x4(c0, c1, c2, c3, bb_ + (br + 16) * 128 + (((c8 + bL3) ^ br7) << 4));
            hmma(acc[2], a0, a1, a2, a3, c0, c1);
            hmma(acc[3], a0, a1, a2, a3, c2, c3);
        }
    }
    const int r0 = m0 + mw_ + qr, r1 = r0 + 8;
#pragma unroll
    for (int nt = 0; nt < 4; nt++) {
        int col = n0 + nw_ + nt * 8 + tg * 2;
        float bx = bias[col], by = bias[col + 1];
        *(__half2*)(C + (size_t)r0 * 512 + col) = __floats2half2_rn(acc[nt][0] + bx, acc[nt][1] + by);
        *(__half2*)(C + (size_t)r1 * 512 + col) = __floats2half2_rn(acc[nt][2] + bx, acc[nt][3] + by);
    }
}

// ---------------- v_mean (2-stage, deterministic, 800 blocks, 5-way ILP) ---------
__global__ void vmean1_kernel() {
    int c = blockIdx.x, d = threadIdx.x;
    float s[5] = {};
#pragma unroll
    for (int i = 0; i < 25; i += 5) {
#pragma unroll
        for (int j = 0; j < 5; j++)
            s[j] += __half2float(g_kv[(size_t)(c * 25 + i + j) * 512 + 256 + d]);
    }
    g_vpart[c * Dsz + d] = ((s[0] + s[1]) + (s[2] + s[3])) + s[4];
}
__global__ void vmean2_kernel() {
    int d = threadIdx.x;
    float s = 0.f;
    for (int c = 0; c < 800; c++) s += g_vpart[c * Dsz + d];
    g_vmean[d] = s * (1.0f / (float)Ssz);
}

// ---------------- split-S attention: fp16 mma, register-P, cp.async pipeline ----
#define A_Q   0
#define A_K   8192
#define A_V   32768
#define A_CT  57344
#define A_LS  73728
#define SM_ATT 74240
#define ONES2 0x3C003C00u

__global__ __launch_bounds__(256, 2) void attn_h2() {
    extern __shared__ __align__(16) char sm[];
    const uint32_t sb = smem_u32(sm);
    const uint32_t qb = sb + A_Q;
    float* ctxs = (float*)(sm + A_CT);
    float* lsm  = (float*)(sm + A_LS);
    const int t = threadIdx.x, w = t >> 5, lane = t & 31;
    const int c = blockIdx.x, bt = blockIdx.y, h = blockIdx.z;
    const int mw_ = (w >> 1) * 16, sh = w & 1;
    const int qr = lane >> 2, tg = lane & 3;
    const int aL4 = (lane >> 4) & 1, bL3 = (lane >> 3) & 1;
    const int ar = mw_ + (lane & 7) + (lane & 8), ar7 = ar & 7;
    const int br = sh * 32 + (lane & 7) + aL4 * 8, br7 = br & 7;
    const int vl7 = lane & 7;
    const int r0 = mw_ + qr, r1 = r0 + 8;

    { // Q tile: fp32 -> half, scale = (1/8)*log2(e)
        const float QS = 0.125f * 1.44269504f;
        char* qc = sm + A_Q;
#pragma unroll
        for (int i = 0; i < 2; i++) {
            int idx = t + i * 256;
            int r = idx >> 3, ch = idx & 7;
            const float* qp = g_q + (size_t)(bt * 64 + r) * 256 + h * 64 + ch * 8;
            float4 x = *(const float4*)qp, y = *(const float4*)(qp + 4);
            *(uint4*)(qc + toff(r, ch)) =
                make_uint4(h2pack(x.x * QS, x.y * QS), h2pack(x.z * QS, x.w * QS),
                           h2pack(y.x * QS, y.y * QS), h2pack(y.z * QS, y.w * QS));
        }
    }
    const int t0 = (TTOT * c) / NCH, t1 = (TTOT * (c + 1)) / NCH;
    const int pr = t >> 3, pch = t & 7;
#pragma unroll
    for (int pf = 0; pf < 2; pf++) {
        int ts = t0 + pf;
        if (ts < t1) {
            uint32_t kd = sb + A_K + pf * 8192, vd = sb + A_V + pf * 8192;
#pragma unroll
            for (int i = 0; i < 2; i++) {
                int r = pr + i * 32;
                const __half* kp = g_kv + (size_t)(ts * 64 + r) * 512 + h * 64 + pch * 8;
                cp_async16(kd + toff(r, pch), kp);
                cp_async16(vd + toff(r, pch), kp + 256);
            }
        }
        CP_COMMIT();
    }
    __syncthreads();          // Q tile visible
    uint32_t qa[4][4];
#pragma unroll
    for (int kk4 = 0; kk4 < 4; kk4++)
        ldsm_x4(qa[kk4][0], qa[kk4][1], qa[kk4][2], qa[kk4][3],
                qb + ar * 128 + ((((kk4 * 2) + aL4) ^ ar7) << 4));

    float ctx[8][4] = {};
    float lacc[4] = {};

    for (int ts = t0; ts < t1; ts++) {
        const int st = (ts - t0) % 3;
        const uint32_t kb = sb + A_K + st * 8192;
        const uint32_t vb = sb + A_V + st * 8192;
        CP_WAIT1();
        __syncthreads();
        { // prefetch ts+2
            int tp = ts + 2;
            if (tp < t1) {
                int sp = (ts - t0 + 2) % 3;
                uint32_t kd = sb + A_K + sp * 8192, vd = sb + A_V + sp * 8192;
#pragma unroll
                for (int i = 0; i < 2; i++) {
                    int r = pr + i * 32;
                    const __half* kp = g_kv + (size_t)(tp * 64 + r) * 512 + h * 64 + pch * 8;
                    cp_async16(kd + toff(r, pch), kp);
                    cp_async16(vd + toff(r, pch), kp + 256);
                }
            }
            CP_COMMIT();
        }
        unsigned mwr0 = g_maskT[(size_t)(2 * ts + sh) * Bq + bt * 64 + r0];
        unsigned mwr1 = g_maskT[(size_t)(2 * ts + sh) * Bq + bt * 64 + r1];
        float scf[4][4] = {};
#pragma unroll
        for (int kk = 0; kk < 64; kk += 16) {
            int c8 = kk >> 3, kq = kk >> 4;
            uint32_t b0, b1, b2, b3, c0, c1, c2, c3;
            ldsm_x4(b0, b1, b2, b3, kb + br * 128 + (((c8 + bL3) ^ br7) << 4));
            hmma(scf[0], qa[kq][0], qa[kq][1], qa[kq][2], qa[kq][3], b0, b1);
            hmma(scf[1], qa[kq][0], qa[kq][1], qa[kq][2], qa[kq][3], b2, b3);
            ldsm_x4(c0, c1, c2, c3, kb + (br + 16) * 128 + (((c8 + bL3) ^ br7) << 4));
            hmma(scf[2], qa[kq][0], qa[kq][1], qa[kq][2], qa[kq][3], c0, c1);
            hmma(scf[3], qa[kq][0], qa[kq][1], qa[kq][2], qa[kq][3], c2, c3);
        }
        uint32_t pa[2][4];
#pragma unroll
        for (int ks2 = 0; ks2 < 2; ks2++) {
#pragma unroll
            for (int q2 = 0; q2 < 2; q2++) {
                int nt = 2 * ks2 + q2;
                int bp = nt * 8 + tg * 2;
                uint32_t am0 = (((mwr0 >> bp) & 1u) ? 0x0000FFFFu : 0u) |
                               (((mwr0 >> (bp + 1)) & 1u) ? 0xFFFF0000u : 0u);
                uint32_t am1 = (((mwr1 >> bp) & 1u) ? 0x0000FFFFu : 0u) |
                               (((mwr1 >> (bp + 1)) & 1u) ? 0xFFFF0000u : 0u);
                pa[ks2][2 * q2]     = ex2h2(cvt_h2(scf[nt][0], scf[nt][1])) & am0;
                pa[ks2][2 * q2 + 1] = ex2h2(cvt_h2(scf[nt][2], scf[nt][3])) & am1;
            }
            hmma(lacc, pa[ks2][0], pa[ks2][1], pa[ks2][2], pa[ks2][3], ONES2, ONES2);
        }
#pragma unroll
        for (int ks2 = 0; ks2 < 2; ks2++) {
            int vrow = sh * 32 + ks2 * 16 + vl7 + bL3 * 8;
            uint32_t A0 = pa[ks2][0], A1 = pa[ks2][1], A2 = pa[ks2][2], A3 = pa[ks2][3];
#pragma unroll
            for (int j = 0; j < 4; j++) {
                uint32_t b0, b1, b2, b3;
                ldsm_x4_t(b0, b1, b2, b3, vb + vrow * 128 + ((((j << 1) + aL4) ^ vl7) << 4));
                hmma(ctx[2 * j],     A0, A1, A2, A3, b0, b1);
                hmma(ctx[2 * j + 1], A0, A1, A2, A3, b2, b3);
            }
        }
    }
    if (sh == 1) {
#pragma unroll
        for (int nc = 0; nc < 8; nc++) {
            *(float2*)&ctxs[r0 * 64 + nc * 8 + tg * 2] = make_float2(ctx[nc][0], ctx[nc][1]);
            *(float2*)&ctxs[r1 * 64 + nc * 8 + tg * 2] = make_float2(ctx[nc][2], ctx[nc][3]);
        }
    }
    if (tg == 0) {
        lsm[sh * 64 + r0] = lacc[0];
        lsm[sh * 64 + r1] = lacc[2];
    }
    __syncthreads();
    if (sh == 0) {
        size_t base = ((size_t)c * Bq + bt * 64) * Dsz + (size_t)h * 64;
#pragma unroll
        for (int nc = 0; nc < 8; nc++) {
            int col = nc * 8 + tg * 2;
            float2 o0 = *(float2*)&ctxs[r0 * 64 + col];
            float2 o1 = *(float2*)&ctxs[r1 * 64 + col];
            *(float2*)(g_part + base + (size_t)r0 * Dsz + col) =
                make_float2(ctx[nc][0] + o0.x, ctx[nc][1] + o0.y);
            *(float2*)(g_part + base + (size_t)r1 * Dsz + col) =
                make_float2(ctx[nc][2] + o1.x, ctx[nc][3] + o1.y);
        }
    }
    if (t < 64)
        g_partl[((size_t)c * Bq + bt * 64 + t) * Hh + h] = lsm[t] + lsm[64 + t];
}

// ---------------- merge partials, normalize (half ctx out) -----------------------
__global__ void reduce_ctx_kernel() {
    int b = blockIdx.x, d = threadIdx.x;
    int h = d >> 6;
    float l = 0.f, s = 0.f;
    for (int c = 0; c < NCH; c++) {
        l += g_partl[((size_t)c * Bq + b) * Hh + h];
        s += g_part[((size_t)c * Bq + b) * Dsz + d];
    }
    float v = (l > 0.f) ? (s / l) : g_vmean[d];
    g_ctx_h[b * Dsz + d] = __float2half_rn(v);
}

// ---------------- launch ---------------------------------------------------------
extern "C" void kernel_launch(void* const* d_in, const int* in_sizes, int n_in,
                              void* d_out, int out_size) {
    const int*   act   = (const int*)d_in[0];
    const float* nc    = (const float*)d_in[1];
    const float* emb   = (const float*)d_in[2];
    const float* w_in  = (const float*)d_in[3];
    const float* b_in  = (const float*)d_in[4];
    const float* w_out = (const float*)d_in[5];
    const float* b_out = (const float*)d_in[6];
    float* out = (float*)d_out;
    (void)in_sizes; (void)n_in; (void)out_size;

    void *p_kv = 0, *p_q = 0;
    void *p_nc = 0, *p_wq = 0, *p_wo = 0, *p_ctx = 0;
    cudaGetSymbolAddress(&p_kv, g_kv);
    cudaGetSymbolAddress(&p_q, g_q);
    cudaGetSymbolAddress(&p_nc, g_nc_h);
    cudaGetSymbolAddress(&p_wq, g_wq_h);
    cudaGetSymbolAddress(&p_wo, g_wo_h);
    cudaGetSymbolAddress(&p_ctx, g_ctx_h);

    cudaFuncSetAttribute(attn_h2, cudaFuncAttributeMaxDynamicSharedMemorySize, SM_ATT);
    cudaFuncSetAttribute(gemm_kv_p, cudaFuncAttributeMaxDynamicSharedMemorySize, 3 * KV_STG);
    cudaFuncSetAttribute(gemm_h, cudaFuncAttributeMaxDynamicSharedMemorySize, 3 * GH_STG);

    pack_mask_kernel<<<Bq, 256>>>(act);
    conv_half<<<CROWS / 4, 256>>>(emb, w_in, nc, w_out);
    gemm_kv_p<<<dim3(8, Spad / 64), 256, 3 * KV_STG>>>(b_in + 256, (__half*)p_kv);
    gemm_h<<<dim3(4, 16), 256, 3 * GH_STG>>>((const __half*)p_nc, (const __half*)p_wq,
                                             b_in, (float*)p_q);
    vmean1_kernel<<<800, 256>>>();
    vmean2_kernel<<<1, 256>>>();
    attn_h2<<<dim3(NCH, Bq / 64, Hh), 256, SM_ATT>>>();
    reduce_ctx_kernel<<<Bq, 256>>>();
    gemm_h<<<dim3(4, 16), 256, 3 * GH_STG>>>((const __half*)p_ctx, (const __half*)p_wo,
                                             b_out, out);
}

// round 13
// speedup vs baseline: 1.0715x; 1.0284x over previous
#include <cuda_runtime.h>
#include <cuda_fp16.h>
#include <cstdint>

#define Bq   1024
#define Ssz  20000
#define Spad 20032          // 64 * 313
#define Dsz  256
#define Hh   4
#define SW2  626            // mask words per batch row incl. padded word
#define NCH  9              // split-S chunks
#define TTOT 313            // 64-row s-tiles total

// ---------------- scratch (static device globals; no allocation) ----------------
__device__ float    g_q[Bq * Dsz];
__device__ __half   g_emb_h[(size_t)Spad * 256];         // half emb, zero-padded
__device__ __half   g_wkv_h[512 * 256];                  // half KV weight rows
__device__ __half   g_nc_h[Bq * 256];                    // half neural_context
__device__ __half   g_wq_h[256 * 256];                   // half Q weight rows
__device__ __half   g_wo_h[256 * 256];                   // half out-proj weights
__device__ __half   g_ctx_h[Bq * Dsz];                   // half ctx (out-proj A)
__device__ __half   g_kv[(size_t)Spad * 512];            // [s][0:256]=k, [256:512]=v
__device__ unsigned g_maskT[SW2 * Bq];                   // word-major: [w][b]
__device__ float    g_part[(size_t)NCH * Bq * Dsz];      // [c][b][h*64+d]
__device__ float    g_partl[NCH * Bq * Hh];
__device__ float    g_vpart[800 * Dsz];
__device__ float    g_vmean[Dsz];

// ---------------- helpers --------------------------------------------------------
__device__ __forceinline__ uint32_t smem_u32(const void* p) {
    uint32_t a;
    asm("{ .reg .u64 t; cvta.to.shared.u64 t, %1; cvt.u32.u64 %0, t; }" : "=r"(a) : "l"(p));
    return a;
}
__device__ __forceinline__ uint32_t h2pack(float a, float b) {
    __half2 h = __floats2half2_rn(a, b);
    return *reinterpret_cast<uint32_t*>(&h);
}
__device__ __forceinline__ uint32_t cvt_h2(float lo, float hi) {
    uint32_t r;
    asm("cvt.rn.f16x2.f32 %0, %1, %2;" : "=r"(r) : "f"(hi), "f"(lo));
    return r;
}
__device__ __forceinline__ uint32_t ex2h2(uint32_t x) {
    uint32_t r;
    asm("ex2.approx.f16x2 %0, %1;" : "=r"(r) : "r"(x));
    return r;
}
// swizzled byte offset inside a 64-col (128B-row) half tile; ch = 8-half chunk
__device__ __forceinline__ int toff(int r, int ch) {
    return r * 128 + ((ch ^ (r & 7)) << 4);
}
__device__ __forceinline__ void ldsm_x4(uint32_t& r0, uint32_t& r1, uint32_t& r2,
                                        uint32_t& r3, uint32_t addr) {
    asm volatile("ldmatrix.sync.aligned.m8n8.x4.shared.b16 {%0,%1,%2,%3}, [%4];"
                 : "=r"(r0), "=r"(r1), "=r"(r2), "=r"(r3) : "r"(addr));
}
__device__ __forceinline__ void ldsm_x4_t(uint32_t& r0, uint32_t& r1, uint32_t& r2,
                                          uint32_t& r3, uint32_t addr) {
    asm volatile("ldmatrix.sync.aligned.m8n8.x4.trans.shared.b16 {%0,%1,%2,%3}, [%4];"
                 : "=r"(r0), "=r"(r1), "=r"(r2), "=r"(r3) : "r"(addr));
}
__device__ __forceinline__ void hmma(float* d, uint32_t a0, uint32_t a1, uint32_t a2,
                                     uint32_t a3, uint32_t b0, uint32_t b1) {
    asm volatile(
        "mma.sync.aligned.m16n8k16.row.col.f32.f16.f16.f32 "
        "{%0,%1,%2,%3},{%4,%5,%6,%7},{%8,%9},{%0,%1,%2,%3};"
        : "+f"(d[0]), "+f"(d[1]), "+f"(d[2]), "+f"(d[3])
        : "r"(a0), "r"(a1), "r"(a2), "r"(a3), "r"(b0), "r"(b1));
}
__device__ __forceinline__ void cp_async16(uint32_t dst, const void* src) {
    asm volatile("cp.async.cg.shared.global [%0], [%1], 16;" :: "r"(dst), "l"(src) : "memory");
}
// zero-fill variant: when pred==0, writes 16 zero bytes without reading src
__device__ __forceinline__ void cp_async16z(uint32_t dst, const void* src, int ok) {
    asm volatile("cp.async.cg.shared.global [%0], [%1], 16, %2;"
                 :: "r"(dst), "l"(src), "r"(ok ? 16 : 0) : "memory");
}
#define CP_COMMIT() asm volatile("cp.async.commit_group;" ::: "memory")
#define CP_WAIT1()  asm volatile("cp.async.wait_group 1;" ::: "memory")

// ---------------- mask bit-packing: int4 loads + nibble assembly -----------------
__global__ void pack_mask_kernel(const int* __restrict__ act) {
    __shared__ unsigned char nib[256];
    const int b = blockIdx.x, t = threadIdx.x;
    const int* row = act + (size_t)b * Ssz;
    for (int it = 0; it < 20; it++) {
        int s = it * 1024 + t * 4;
        unsigned n = 0;
        if (s + 3 < Ssz) {
            int4 a = *(const int4*)(row + s);
            n = (unsigned)(a.x > 0) | ((unsigned)(a.y > 0) << 1) |
                ((unsigned)(a.z > 0) << 2) | ((unsigned)(a.w > 0) << 3);
        } else {
#pragma unroll
            for (int j = 0; j < 4; j++) {
                int ss = s + j;
                if (ss < Ssz && row[ss] > 0) n |= 1u << j;
            }
        }
        nib[t] = (unsigned char)n;
        __syncthreads();
        if (t < 32) {
            int w = it * 32 + t;
            if (w < SW2) {
                uint2 v = *(const uint2*)(nib + t * 8);
                unsigned lo = v.x, hi = v.y;
                unsigned word = (lo & 0xFu) | (((lo >> 8) & 0xFu) << 4) |
                                (((lo >> 16) & 0xFu) << 8) | (((lo >> 24) & 0xFu) << 12) |
                                ((hi & 0xFu) << 16) | (((hi >> 8) & 0xFu) << 20) |
                                (((hi >> 16) & 0xFu) << 24) | (((hi >> 24) & 0xFu) << 28);
                g_maskT[w * Bq + b] = word;
            }
        }
        __syncthreads();
    }
}

// ---------------- fp32 -> fp16 pre-conversion ------------------------------------
#define CROWS (Spad + 512 + Bq + 256 + 256)
__global__ void conv_half(const float* __restrict__ emb, const float* __restrict__ w_in,
                          const float* __restrict__ nc, const float* __restrict__ w_out) {
    int idx = blockIdx.x * 256 + threadIdx.x;
    int r = idx >> 6, c = (idx & 63) * 4;
    if (r < Spad) {
        float4 v = make_float4(0.f, 0.f, 0.f, 0.f);
        if (r < Ssz) v = *(const float4*)(emb + (size_t)r * 256 + c);
        *(uint2*)(g_emb_h + (size_t)r * 256 + c) = make_uint2(h2pack(v.x, v.y), h2pack(v.z, v.w));
    } else if (r < Spad + 512) {
        int rw = r - Spad;
        float4 v = *(const float4*)(w_in + (size_t)(256 + rw) * 256 + c);
        *(uint2*)(g_wkv_h + rw * 256 + c) = make_uint2(h2pack(v.x, v.y), h2pack(v.z, v.w));
    } else if (r < Spad + 512 + Bq) {
        int rn = r - Spad - 512;
        float4 v = *(const float4*)(nc + (size_t)rn * 256 + c);
        *(uint2*)(g_nc_h + rn * 256 + c) = make_uint2(h2pack(v.x, v.y), h2pack(v.z, v.w));
    } else if (r < Spad + 512 + Bq + 256) {
        int rw = r - Spad - 512 - Bq;
        float4 v = *(const float4*)(w_in + (size_t)rw * 256 + c);
        *(uint2*)(g_wq_h + rw * 256 + c) = make_uint2(h2pack(v.x, v.y), h2pack(v.z, v.w));
    } else if (r < CROWS) {
        int rw = r - Spad - 512 - Bq - 256;
        float4 v = *(const float4*)(w_out + (size_t)rw * 256 + c);
        *(uint2*)(g_wo_h + rw * 256 + c) = make_uint2(h2pack(v.x, v.y), h2pack(v.z, v.w));
    }
}

// ---------------- fp16 GEMM, fp32 out: C[1024 x 256], M32xN64 tiles --------------
// 128 CTAs (vs 64): latency-bound kernel, more resident parallelism.
#define GH_STG 12288   // A 4KB + B 8KB per stage
__global__ __launch_bounds__(256) void gemm_h(const __half* __restrict__ Ah,
                                              const __half* __restrict__ Bh,
                                              const float* __restrict__ bias,
                                              float* __restrict__ C) {
    extern __shared__ __align__(16) char sm[];
    const uint32_t sb = smem_u32(sm);
    const int t = threadIdx.x, w = t >> 5, lane = t & 31;
    const int m0 = blockIdx.y * 32, n0 = blockIdx.x * 64;
    const int mw_ = (w >> 2) * 16, nw_ = (w & 3) * 16;
    const int qr = lane >> 2, tg = lane & 3;
    const int aL4 = (lane >> 4) & 1, bL3 = (lane >> 3) & 1;
    const int ar = mw_ + (lane & 7) + (lane & 8), ar7 = ar & 7;
    const int br = nw_ + (lane & 7) + aL4 * 8, br7 = br & 7;
    const int pr = t >> 3, pch = t & 7;
#pragma unroll
    for (int pf = 0; pf < 2; pf++) {
        uint32_t base = sb + pf * GH_STG;
        cp_async16(base + toff(pr, pch), Ah + (size_t)(m0 + pr) * 256 + pf * 64 + pch * 8);
#pragma unroll
        for (int i = 0; i < 2; i++) {
            int r = pr + i * 32;
            cp_async16(base + 4096 + toff(r, pch), Bh + (n0 + r) * 256 + pf * 64 + pch * 8);
        }
        CP_COMMIT();
    }
    float acc[2][4] = {};
    for (int k0 = 0; k0 < 4; k0++) {
        const uint32_t ab = sb + (k0 % 3) * GH_STG, bb_ = ab + 4096;
        CP_WAIT1();
        __syncthreads();
        {
            int kp = k0 + 2;
            if (kp < 4) {
                uint32_t base = sb + (kp % 3) * GH_STG;
                cp_async16(base + toff(pr, pch), Ah + (size_t)(m0 + pr) * 256 + kp * 64 + pch * 8);
#pragma unroll
                for (int i = 0; i < 2; i++) {
                    int r = pr + i * 32;
                    cp_async16(base + 4096 + toff(r, pch), Bh + (n0 + r) * 256 + kp * 64 + pch * 8);
                }
            }
            CP_COMMIT();
        }
#pragma unroll
        for (int kk = 0; kk < 64; kk += 16) {
            int c8 = kk >> 3;
            uint32_t a0, a1, a2, a3, b0, b1, b2, b3;
            ldsm_x4(a0, a1, a2, a3, ab + ar * 128 + (((c8 + aL4) ^ ar7) << 4));
            ldsm_x4(b0, b1, b2, b3, bb_ + br * 128 + (((c8 + bL3) ^ br7) << 4));
            hmma(acc[0], a0, a1, a2, a3, b0, b1);
            hmma(acc[1], a0, a1, a2, a3, b2, b3);
        }
    }
    const int r0 = m0 + mw_ + qr, r1 = r0 + 8;
#pragma unroll
    for (int nt = 0; nt < 2; nt++) {
        int col = n0 + nw_ + nt * 8 + tg * 2;
        float bx = bias[col], by = bias[col + 1];
        *(float2*)(C + (size_t)r0 * 256 + col) = make_float2(acc[nt][0] + bx, acc[nt][1] + by);
        *(float2*)(C + (size_t)r1 * 256 + col) = make_float2(acc[nt][2] + bx, acc[nt][3] + by);
    }
}

// ---------------- KV projection: M128xN64 tiles, M32 warp tiles ------------------
// A-fragment row-half pattern (ar / ar+16) validated in R10's attn_h3.
#define KV_STG 24576   // A 16KB + B 8KB per stage
__global__ __launch_bounds__(256) void gemm_kv_p(const float* __restrict__ bias,
                                                 __half* __restrict__ C) {
    extern __shared__ __align__(16) char sm[];
    const uint32_t sb = smem_u32(sm);
    const int t = threadIdx.x, w = t >> 5, lane = t & 31;
    const int m0 = blockIdx.y * 128, n0 = blockIdx.x * 64;
    const int mw_ = (w >> 1) * 32, nw_ = (w & 1) * 32;
    const int qr = lane >> 2, tg = lane & 3;
    const int aL4 = (lane >> 4) & 1, bL3 = (lane >> 3) & 1;
    const int ar = mw_ + (lane & 7) + (lane & 8), ar7 = ar & 7;
    const int br = nw_ + (lane & 7) + aL4 * 8, br7 = br & 7;
    const int pr = t >> 3, pch = t & 7;
#pragma unroll
    for (int pf = 0; pf < 2; pf++) {
        uint32_t base = sb + pf * KV_STG;
#pragma unroll
        for (int i = 0; i < 4; i++) {   // A: 128 rows, zfill past Spad
            int r = pr + i * 32;
            int grow = m0 + r;
            int ok = grow < Spad;
            const __half* src = g_emb_h + (size_t)(ok ? grow : 0) * 256 + pf * 64 + pch * 8;
            cp_async16z(base + toff(r, pch), src, ok);
        }
#pragma unroll
        for (int i = 0; i < 2; i++) {   // B: 64 weight rows
            int r = pr + i * 32;
            cp_async16(base + 16384 + toff(r, pch),
                       g_wkv_h + (n0 + r) * 256 + pf * 64 + pch * 8);
        }
        CP_COMMIT();
    }
    float acc[2][4][4] = {};
    for (int k0 = 0; k0 < 4; k0++) {
        const uint32_t ab = sb + (k0 % 3) * KV_STG, bb_ = ab + 16384;
        CP_WAIT1();
        __syncthreads();
        {
            int kp = k0 + 2;
            if (kp < 4) {
                uint32_t base = sb + (kp % 3) * KV_STG;
#pragma unroll
                for (int i = 0; i < 4; i++) {
                    int r = pr + i * 32;
                    int grow = m0 + r;
                    int ok = grow < Spad;
                    const __half* src = g_emb_h + (size_t)(ok ? grow : 0) * 256 + kp * 64 + pch * 8;
                    cp_async16z(base + toff(r, pch), src, ok);
                }
#pragma unroll
                for (int i = 0; i < 2; i++) {
                    int r = pr + i * 32;
                    cp_async16(base + 16384 + toff(r, pch),
                               g_wkv_h + (n0 + r) * 256 + kp * 64 + pch * 8);
                }
            }
            CP_COMMIT();
        }
#pragma unroll
        for (int kk = 0; kk < 64; kk += 16) {
            int c8 = kk >> 3;
            uint32_t a0, a1, a2, a3, e0, e1, e2, e3;
            uint32_t b0, b1, b2, b3, c0, c1, c2, c3;
            uint32_t axo = ((c8 + aL4) ^ ar7) << 4;
            ldsm_x4(a0, a1, a2, a3, ab + ar * 128 + axo);
            ldsm_x4(e0, e1, e2, e3, ab + (ar + 16) * 128 + axo);
            ldsm_x4(b0, b1, b2, b3, bb_ + br * 128 + (((c8 + bL3) ^ br7) << 4));
            ldsm_x4(c0, c1, c2, c3, bb_ + (br + 16) * 128 + (((c8 + bL3) ^ br7) << 4));
            hmma(acc[0][0], a0, a1, a2, a3, b0, b1);
            hmma(acc[0][1], a0, a1, a2, a3, b2, b3);
            hmma(acc[0][2], a0, a1, a2, a3, c0, c1);
            hmma(acc[0][3], a0, a1, a2, a3, c2, c3);
            hmma(acc[1][0], e0, e1, e2, e3, b0, b1);
            hmma(acc[1][1], e0, e1, e2, e3, b2, b3);
            hmma(acc[1][2], e0, e1, e2, e3, c0, c1);
            hmma(acc[1][3], e0, e1, e2, e3, c2, c3);
        }
    }
#pragma unroll
    for (int rh = 0; rh < 2; rh++) {
        const int r0 = m0 + mw_ + rh * 16 + qr, r1 = r0 + 8;
#pragma unroll
        for (int nt = 0; nt < 4; nt++) {
            int col = n0 + nw_ + nt * 8 + tg * 2;
            float bx = bias[col], by = bias[col + 1];
            if (r0 < Spad)
                *(__half2*)(C + (size_t)r0 * 512 + col) =
                    __floats2half2_rn(acc[rh][nt][0] + bx, acc[rh][nt][1] + by);
            if (r1 < Spad)
                *(__half2*)(C + (size_t)r1 * 512 + col) =
                    __floats2half2_rn(acc[rh][nt][2] + bx, acc[rh][nt][3] + by);
        }
    }
}

// ---------------- v_mean (2-stage, deterministic, 800 blocks, 5-way ILP) ---------
__global__ void vmean1_kernel() {
    int c = blockIdx.x, d = threadIdx.x;
    float s[5] = {};
#pragma unroll
    for (int i = 0; i < 25; i += 5) {
#pragma unroll
        for (int j = 0; j < 5; j++)
            s[j] += __half2float(g_kv[(size_t)(c * 25 + i + j) * 512 + 256 + d]);
    }
    g_vpart[c * Dsz + d] = ((s[0] + s[1]) + (s[2] + s[3])) + s[4];
}
__global__ void vmean2_kernel() {
    int d = threadIdx.x;
    float s = 0.f;
    for (int c = 0; c < 800; c++) s += g_vpart[c * Dsz + d];
    g_vmean[d] = s * (1.0f / (float)Ssz);
}

// ---------------- split-S attention: fp16 mma, register-P, cp.async pipeline ----
#define A_Q   0
#define A_K   8192
#define A_V   32768
#define A_CT  57344
#define A_LS  73728
#define SM_ATT 74240
#define ONES2 0x3C003C00u

__global__ __launch_bounds__(256, 2) void attn_h2() {
    extern __shared__ __align__(16) char sm[];
    const uint32_t sb = smem_u32(sm);
    const uint32_t qb = sb + A_Q;
    float* ctxs = (float*)(sm + A_CT);
    float* lsm  = (float*)(sm + A_LS);
    const int t = threadIdx.x, w = t >> 5, lane = t & 31;
    const int c = blockIdx.x, bt = blockIdx.y, h = blockIdx.z;
    const int mw_ = (w >> 1) * 16, sh = w & 1;
    const int qr = lane >> 2, tg = lane & 3;
    const int aL4 = (lane >> 4) & 1, bL3 = (lane >> 3) & 1;
    const int ar = mw_ + (lane & 7) + (lane & 8), ar7 = ar & 7;
    const int br = sh * 32 + (lane & 7) + aL4 * 8, br7 = br & 7;
    const int vl7 = lane & 7;
    const int r0 = mw_ + qr, r1 = r0 + 8;

    { // Q tile: fp32 -> half, scale = (1/8)*log2(e)
        const float QS = 0.125f * 1.44269504f;
        char* qc = sm + A_Q;
#pragma unroll
        for (int i = 0; i < 2; i++) {
            int idx = t + i * 256;
            int r = idx >> 3, ch = idx & 7;
            const float* qp = g_q + (size_t)(bt * 64 + r) * 256 + h * 64 + ch * 8;
            float4 x = *(const float4*)qp, y = *(const float4*)(qp + 4);
            *(uint4*)(qc + toff(r, ch)) =
                make_uint4(h2pack(x.x * QS, x.y * QS), h2pack(x.z * QS, x.w * QS),
                           h2pack(y.x * QS, y.y * QS), h2pack(y.z * QS, y.w * QS));
        }
    }
    const int t0 = (TTOT * c) / NCH, t1 = (TTOT * (c + 1)) / NCH;
    const int pr = t >> 3, pch = t & 7;
#pragma unroll
    for (int pf = 0; pf < 2; pf++) {
        int ts = t0 + pf;
        if (ts < t1) {
            uint32_t kd = sb + A_K + pf * 8192, vd = sb + A_V + pf * 8192;
#pragma unroll
            for (int i = 0; i < 2; i++) {
                int r = pr + i * 32;
                const __half* kp = g_kv + (size_t)(ts * 64 + r) * 512 + h * 64 + pch * 8;
                cp_async16(kd + toff(r, pch), kp);
                cp_async16(vd + toff(r, pch), kp + 256);
            }
        }
        CP_COMMIT();
    }
    __syncthreads();          // Q tile visible
    uint32_t qa[4][4];
#pragma unroll
    for (int kk4 = 0; kk4 < 4; kk4++)
        ldsm_x4(qa[kk4][0], qa[kk4][1], qa[kk4][2], qa[kk4][3],
                qb + ar * 128 + ((((kk4 * 2) + aL4) ^ ar7) << 4));

    float ctx[8][4] = {};
    float lacc[4] = {};

    for (int ts = t0; ts < t1; ts++) {
        const int st = (ts - t0) % 3;
        const uint32_t kb = sb + A_K + st * 8192;
        const uint32_t vb = sb + A_V + st * 8192;
        CP_WAIT1();
        __syncthreads();
        { // prefetch ts+2
            int tp = ts + 2;
            if (tp < t1) {
                int sp = (ts - t0 + 2) % 3;
                uint32_t kd = sb + A_K + sp * 8192, vd = sb + A_V + sp * 8192;
#pragma unroll
                for (int i = 0; i < 2; i++) {
                    int r = pr + i * 32;
                    const __half* kp = g_kv + (size_t)(tp * 64 + r) * 512 + h * 64 + pch * 8;
                    cp_async16(kd + toff(r, pch), kp);
                    cp_async16(vd + toff(r, pch), kp + 256);
                }
            }
            CP_COMMIT();
        }
        unsigned mwr0 = g_maskT[(size_t)(2 * ts + sh) * Bq + bt * 64 + r0];
        unsigned mwr1 = g_maskT[(size_t)(2 * ts + sh) * Bq + bt * 64 + r1];
        float scf[4][4] = {};
#pragma unroll
        for (int kk = 0; kk < 64; kk += 16) {
            int c8 = kk >> 3, kq = kk >> 4;
            uint32_t b0, b1, b2, b3, c0, c1, c2, c3;
            ldsm_x4(b0, b1, b2, b3, kb + br * 128 + (((c8 + bL3) ^ br7) << 4));
            hmma(scf[0], qa[kq][0], qa[kq][1], qa[kq][2], qa[kq][3], b0, b1);
            hmma(scf[1], qa[kq][0], qa[kq][1], qa[kq][2], qa[kq][3], b2, b3);
            ldsm_x4(c0, c1, c2, c3, kb + (br + 16) * 128 + (((c8 + bL3) ^ br7) << 4));
            hmma(scf[2], qa[kq][0], qa[kq][1], qa[kq][2], qa[kq][3], c0, c1);
            hmma(scf[3], qa[kq][0], qa[kq][1], qa[kq][2], qa[kq][3], c2, c3);
        }
        uint32_t pa[2][4];
#pragma unroll
        for (int ks2 = 0; ks2 < 2; ks2++) {
#pragma unroll
            for (int q2 = 0; q2 < 2; q2++) {
                int nt = 2 * ks2 + q2;
                int bp = nt * 8 + tg * 2;
                uint32_t am0 = (((mwr0 >> bp) & 1u) ? 0x0000FFFFu : 0u) |
                               (((mwr0 >> (bp + 1)) & 1u) ? 0xFFFF0000u : 0u);
                uint32_t am1 = (((mwr1 >> bp) & 1u) ? 0x0000FFFFu : 0u) |
                               (((mwr1 >> (bp + 1)) & 1u) ? 0xFFFF0000u : 0u);
                pa[ks2][2 * q2]     = ex2h2(cvt_h2(scf[nt][0], scf[nt][1])) & am0;
                pa[ks2][2 * q2 + 1] = ex2h2(cvt_h2(scf[nt][2], scf[nt][3])) & am1;
            }
            hmma(lacc, pa[ks2][0], pa[ks2][1], pa[ks2][2], pa[ks2][3], ONES2, ONES2);
        }
#pragma unroll
        for (int ks2 = 0; ks2 < 2; ks2++) {
            int vrow = sh * 32 + ks2 * 16 + vl7 + bL3 * 8;
            uint32_t A0 = pa[ks2][0], A1 = pa[ks2][1], A2 = pa[ks2][2], A3 = pa[ks2][3];
#pragma unroll
            for (int j = 0; j < 4; j++) {
                uint32_t b0, b1, b2, b3;
                ldsm_x4_t(b0, b1, b2, b3, vb + vrow * 128 + ((((j << 1) + aL4) ^ vl7) << 4));
                hmma(ctx[2 * j],     A0, A1, A2, A3, b0, b1);
                hmma(ctx[2 * j + 1], A0, A1, A2, A3, b2, b3);
            }
        }
    }
    if (sh == 1) {
#pragma unroll
        for (int nc = 0; nc < 8; nc++) {
            *(float2*)&ctxs[r0 * 64 + nc * 8 + tg * 2] = make_float2(ctx[nc][0], ctx[nc][1]);
            *(float2*)&ctxs[r1 * 64 + nc * 8 + tg * 2] = make_float2(ctx[nc][2], ctx[nc][3]);
        }
    }
    if (tg == 0) {
        lsm[sh * 64 + r0] = lacc[0];
        lsm[sh * 64 + r1] = lacc[2];
    }
    __syncthreads();
    if (sh == 0) {
        size_t base = ((size_t)c * Bq + bt * 64) * Dsz + (size_t)h * 64;
#pragma unroll
        for (int nc = 0; nc < 8; nc++) {
            int col = nc * 8 + tg * 2;
            float2 o0 = *(float2*)&ctxs[r0 * 64 + col];
            float2 o1 = *(float2*)&ctxs[r1 * 64 + col];
            *(float2*)(g_part + base + (size_t)r0 * Dsz + col) =
                make_float2(ctx[nc][0] + o0.x, ctx[nc][1] + o0.y);
            *(float2*)(g_part + base + (size_t)r1 * Dsz + col) =
                make_float2(ctx[nc][2] + o1.x, ctx[nc][3] + o1.y);
        }
    }
    if (t < 64)
        g_partl[((size_t)c * Bq + bt * 64 + t) * Hh + h] = lsm[t] + lsm[64 + t];
}

// ---------------- merge partials, normalize (half ctx out) -----------------------
__global__ void reduce_ctx_kernel() {
    int b = blockIdx.x, d = threadIdx.x;
    int h = d >> 6;
    float l = 0.f, s = 0.f;
    for (int c = 0; c < NCH; c++) {
        l += g_partl[((size_t)c * Bq + b) * Hh + h];
        s += g_part[((size_t)c * Bq + b) * Dsz + d];
    }
    float v = (l > 0.f) ? (s / l) : g_vmean[d];
    g_ctx_h[b * Dsz + d] = __float2half_rn(v);
}

// ---------------- launch ---------------------------------------------------------
extern "C" void kernel_launch(void* const* d_in, const int* in_sizes, int n_in,
                              void* d_out, int out_size) {
    const int*   act   = (const int*)d_in[0];
    const float* nc    = (const float*)d_in[1];
    const float* emb   = (const float*)d_in[2];
    const float* w_in  = (const float*)d_in[3];
    const float* b_in  = (const float*)d_in[4];
    const float* w_out = (const float*)d_in[5];
    const float* b_out = (const float*)d_in[6];
    float* out = (float*)d_out;
    (void)in_sizes; (void)n_in; (void)out_size;

    void *p_kv = 0, *p_q = 0;
    void *p_nc = 0, *p_wq = 0, *p_wo = 0, *p_ctx = 0;
    cudaGetSymbolAddress(&p_kv, g_kv);
    cudaGetSymbolAddress(&p_q, g_q);
    cudaGetSymbolAddress(&p_nc, g_nc_h);
    cudaGetSymbolAddress(&p_wq, g_wq_h);
    cudaGetSymbolAddress(&p_wo, g_wo_h);
    cudaGetSymbolAddress(&p_ctx, g_ctx_h);

    cudaFuncSetAttribute(attn_h2, cudaFuncAttributeMaxDynamicSharedMemorySize, SM_ATT);
    cudaFuncSetAttribute(gemm_kv_p, cudaFuncAttributeMaxDynamicSharedMemorySize, 3 * KV_STG);
    cudaFuncSetAttribute(gemm_h, cudaFuncAttributeMaxDynamicSharedMemorySize, 3 * GH_STG);

    pack_mask_kernel<<<Bq, 256>>>(act);
    conv_half<<<CROWS / 4, 256>>>(emb, w_in, nc, w_out);
    gemm_kv_p<<<dim3(8, 157), 256, 3 * KV_STG>>>(b_in + 256, (__half*)p_kv);
    gemm_h<<<dim3(4, 32), 256, 3 * GH_STG>>>((const __half*)p_nc, (const __half*)p_wq,
                                             b_in, (float*)p_q);
    vmean1_kernel<<<800, 256>>>();
    vmean2_kernel<<<1, 256>>>();
    attn_h2<<<dim3(NCH, Bq / 64, Hh), 256, SM_ATT>>>();
    reduce_ctx_kernel<<<Bq, 256>>>();
    gemm_h<<<dim3(4, 32), 256, 3 * GH_STG>>>((const __half*)p_ctx, (const __half*)p_wo,
                                             b_out, out);
}

// round 14
// speedup vs baseline: 1.0815x; 1.0093x over previous
#include <cuda_runtime.h>
#include <cuda_fp16.h>
#include <cstdint>

#define Bq   1024
#define Ssz  20000
#define Spad 20032          // 64 * 313
#define Dsz  256
#define Hh   4
#define SW2  626            // mask words per batch row incl. padded word
#define NCH  9              // split-S chunks
#define TTOT 313            // 64-row s-tiles total

// ---------------- scratch (static device globals; no allocation) ----------------
__device__ float    g_q[Bq * Dsz];
__device__ __half   g_emb_h[(size_t)Spad * 256];         // half emb, zero-padded
__device__ __half   g_wkv_h[512 * 256];                  // half KV weight rows
__device__ __half   g_nc_h[Bq * 256];                    // half neural_context
__device__ __half   g_wq_h[256 * 256];                   // half Q weight rows
__device__ __half   g_wo_h[256 * 256];                   // half out-proj weights
__device__ __half   g_ctx_h[Bq * Dsz];                   // half ctx (out-proj A)
__device__ __half   g_kv[(size_t)Spad * 512];            // [s][0:256]=k, [256:512]=v
__device__ unsigned g_maskT[SW2 * Bq];                   // word-major: [w][b]
__device__ float    g_part[(size_t)NCH * Bq * Dsz];      // [c][b][h*64+d]
__device__ float    g_partl[NCH * Bq * Hh];
__device__ float    g_vpart[800 * Dsz];
__device__ float    g_vmean[Dsz];

// ---------------- helpers --------------------------------------------------------
__device__ __forceinline__ uint32_t smem_u32(const void* p) {
    uint32_t a;
    asm("{ .reg .u64 t; cvta.to.shared.u64 t, %1; cvt.u32.u64 %0, t; }" : "=r"(a) : "l"(p));
    return a;
}
__device__ __forceinline__ uint32_t h2pack(float a, float b) {
    __half2 h = __floats2half2_rn(a, b);
    return *reinterpret_cast<uint32_t*>(&h);
}
__device__ __forceinline__ uint32_t ex2h2(uint32_t x) {
    uint32_t r;
    asm("ex2.approx.f16x2 %0, %1;" : "=r"(r) : "r"(x));
    return r;
}
// swizzled byte offset inside a 64-col (128B-row) half tile; ch = 8-half chunk
__device__ __forceinline__ int toff(int r, int ch) {
    return r * 128 + ((ch ^ (r & 7)) << 4);
}
__device__ __forceinline__ void ldsm_x4(uint32_t& r0, uint32_t& r1, uint32_t& r2,
                                        uint32_t& r3, uint32_t addr) {
    asm volatile("ldmatrix.sync.aligned.m8n8.x4.shared.b16 {%0,%1,%2,%3}, [%4];"
                 : "=r"(r0), "=r"(r1), "=r"(r2), "=r"(r3) : "r"(addr));
}
__device__ __forceinline__ void ldsm_x4_t(uint32_t& r0, uint32_t& r1, uint32_t& r2,
                                          uint32_t& r3, uint32_t addr) {
    asm volatile("ldmatrix.sync.aligned.m8n8.x4.trans.shared.b16 {%0,%1,%2,%3}, [%4];"
                 : "=r"(r0), "=r"(r1), "=r"(r2), "=r"(r3) : "r"(addr));
}
__device__ __forceinline__ void hmma(float* d, uint32_t a0, uint32_t a1, uint32_t a2,
                                     uint32_t a3, uint32_t b0, uint32_t b1) {
    asm volatile(
        "mma.sync.aligned.m16n8k16.row.col.f32.f16.f16.f32 "
        "{%0,%1,%2,%3},{%4,%5,%6,%7},{%8,%9},{%0,%1,%2,%3};"
        : "+f"(d[0]), "+f"(d[1]), "+f"(d[2]), "+f"(d[3])
        : "r"(a0), "r"(a1), "r"(a2), "r"(a3), "r"(b0), "r"(b1));
}
// f16-accumulator variant: D/C are 2 regs; d[0]=(r0,c..c+1) half2, d[1]=(r1,...)
__device__ __forceinline__ void hmma_h16(uint32_t* d, uint32_t a0, uint32_t a1,
                                         uint32_t a2, uint32_t a3,
                                         uint32_t b0, uint32_t b1) {
    asm volatile(
        "mma.sync.aligned.m16n8k16.row.col.f16.f16.f16.f16 "
        "{%0,%1},{%2,%3,%4,%5},{%6,%7},{%0,%1};"
        : "+r"(d[0]), "+r"(d[1])
        : "r"(a0), "r"(a1), "r"(a2), "r"(a3), "r"(b0), "r"(b1));
}
__device__ __forceinline__ void cp_async16(uint32_t dst, const void* src) {
    asm volatile("cp.async.cg.shared.global [%0], [%1], 16;" :: "r"(dst), "l"(src) : "memory");
}
// zero-fill variant: when pred==0, writes 16 zero bytes without reading src
__device__ __forceinline__ void cp_async16z(uint32_t dst, const void* src, int ok) {
    asm volatile("cp.async.cg.shared.global [%0], [%1], 16, %2;"
                 :: "r"(dst), "l"(src), "r"(ok ? 16 : 0) : "memory");
}
#define CP_COMMIT() asm volatile("cp.async.commit_group;" ::: "memory")
#define CP_WAIT1()  asm volatile("cp.async.wait_group 1;" ::: "memory")
#define CP_WAIT0()  asm volatile("cp.async.wait_group 0;" ::: "memory")

// ---------------- mask bit-packing: int4 loads + nibble assembly -----------------
__global__ void pack_mask_kernel(const int* __restrict__ act) {
    __shared__ unsigned char nib[256];
    const int b = blockIdx.x, t = threadIdx.x;
    const int* row = act + (size_t)b * Ssz;
    for (int it = 0; it < 20; it++) {
        int s = it * 1024 + t * 4;
        unsigned n = 0;
        if (s + 3 < Ssz) {
            int4 a = *(const int4*)(row + s);
            n = (unsigned)(a.x > 0) | ((unsigned)(a.y > 0) << 1) |
                ((unsigned)(a.z > 0) << 2) | ((unsigned)(a.w > 0) << 3);
        } else {
#pragma unroll
            for (int j = 0; j < 4; j++) {
                int ss = s + j;
                if (ss < Ssz && row[ss] > 0) n |= 1u << j;
            }
        }
        nib[t] = (unsigned char)n;
        __syncthreads();
        if (t < 32) {
            int w = it * 32 + t;
            if (w < SW2) {
                uint2 v = *(const uint2*)(nib + t * 8);
                unsigned lo = v.x, hi = v.y;
                unsigned word = (lo & 0xFu) | (((lo >> 8) & 0xFu) << 4) |
                                (((lo >> 16) & 0xFu) << 8) | (((lo >> 24) & 0xFu) << 12) |
                                ((hi & 0xFu) << 16) | (((hi >> 8) & 0xFu) << 20) |
                                (((hi >> 16) & 0xFu) << 24) | (((hi >> 24) & 0xFu) << 28);
                g_maskT[w * Bq + b] = word;
            }
        }
        __syncthreads();
    }
}

// ---------------- fp32 -> fp16 pre-conversion ------------------------------------
#define CROWS (Spad + 512 + Bq + 256 + 256)
__global__ void conv_half(const float* __restrict__ emb, const float* __restrict__ w_in,
                          const float* __restrict__ nc, const float* __restrict__ w_out) {
    int idx = blockIdx.x * 256 + threadIdx.x;
    int r = idx >> 6, c = (idx & 63) * 4;
    if (r < Spad) {
        float4 v = make_float4(0.f, 0.f, 0.f, 0.f);
        if (r < Ssz) v = *(const float4*)(emb + (size_t)r * 256 + c);
        *(uint2*)(g_emb_h + (size_t)r * 256 + c) = make_uint2(h2pack(v.x, v.y), h2pack(v.z, v.w));
    } else if (r < Spad + 512) {
        int rw = r - Spad;
        float4 v = *(const float4*)(w_in + (size_t)(256 + rw) * 256 + c);
        *(uint2*)(g_wkv_h + rw * 256 + c) = make_uint2(h2pack(v.x, v.y), h2pack(v.z, v.w));
    } else if (r < Spad + 512 + Bq) {
        int rn = r - Spad - 512;
        float4 v = *(const float4*)(nc + (size_t)rn * 256 + c);
        *(uint2*)(g_nc_h + rn * 256 + c) = make_uint2(h2pack(v.x, v.y), h2pack(v.z, v.w));
    } else if (r < Spad + 512 + Bq + 256) {
        int rw = r - Spad - 512 - Bq;
        float4 v = *(const float4*)(w_in + (size_t)rw * 256 + c);
        *(uint2*)(g_wq_h + rw * 256 + c) = make_uint2(h2pack(v.x, v.y), h2pack(v.z, v.w));
    } else if (r < CROWS) {
        int rw = r - Spad - 512 - Bq - 256;
        float4 v = *(const float4*)(w_out + (size_t)rw * 256 + c);
        *(uint2*)(g_wo_h + rw * 256 + c) = make_uint2(h2pack(v.x, v.y), h2pack(v.z, v.w));
    }
}

// ---------------- fp16 GEMM, fp32 out: single-shot M32xN64, K=256 resident -------
// A 16KB + B 32KB = 48KB static smem; one load wave, one sync, 16 MMA k-steps.
__global__ __launch_bounds__(256) void gemm_h(const __half* __restrict__ Ah,
                                              const __half* __restrict__ Bh,
                                              const float* __restrict__ bias,
                                              float* __restrict__ C) {
    __shared__ __align__(16) char sm[49152];
    const uint32_t sb = smem_u32(sm);
    const int t = threadIdx.x, w = t >> 5, lane = t & 31;
    const int m0 = blockIdx.y * 32, n0 = blockIdx.x * 64;
    const int mw_ = (w >> 2) * 16, nw_ = (w & 3) * 16;
    const int qr = lane >> 2, tg = lane & 3;
    const int aL4 = (lane >> 4) & 1, bL3 = (lane >> 3) & 1;
    const int ar = mw_ + (lane & 7) + (lane & 8), ar7 = ar & 7;
    const int br = nw_ + (lane & 7) + aL4 * 8, br7 = br & 7;
    const int pr = t >> 3, pch = t & 7;
#pragma unroll
    for (int cc = 0; cc < 4; cc++) {
        cp_async16(sb + cc * 4096 + toff(pr, pch),
                   Ah + (size_t)(m0 + pr) * 256 + cc * 64 + pch * 8);
#pragma unroll
        for (int i = 0; i < 2; i++) {
            int r = pr + i * 32;
            cp_async16(sb + 16384 + cc * 8192 + toff(r, pch),
                       Bh + (n0 + r) * 256 + cc * 64 + pch * 8);
        }
    }
    CP_COMMIT();
    CP_WAIT0();
    __syncthreads();
    float acc[2][4] = {};
#pragma unroll
    for (int kk = 0; kk < 256; kk += 16) {
        int cc = kk >> 6, c8 = (kk & 63) >> 3;
        uint32_t a0, a1, a2, a3, b0, b1, b2, b3;
        ldsm_x4(a0, a1, a2, a3, sb + cc * 4096 + ar * 128 + (((c8 + aL4) ^ ar7) << 4));
        ldsm_x4(b0, b1, b2, b3, sb + 16384 + cc * 8192 + br * 128 + (((c8 + bL3) ^ br7) << 4));
        hmma(acc[0], a0, a1, a2, a3, b0, b1);
        hmma(acc[1], a0, a1, a2, a3, b2, b3);
    }
    const int r0 = m0 + mw_ + qr, r1 = r0 + 8;
#pragma unroll
    for (int nt = 0; nt < 2; nt++) {
        int col = n0 + nw_ + nt * 8 + tg * 2;
        float bx = bias[col], by = bias[col + 1];
        *(float2*)(C + (size_t)r0 * 256 + col) = make_float2(acc[nt][0] + bx, acc[nt][1] + by);
        *(float2*)(C + (size_t)r1 * 256 + col) = make_float2(acc[nt][2] + bx, acc[nt][3] + by);
    }
}

// ---------------- KV projection: M128xN64 tiles, M32 warp tiles ------------------
#define KV_STG 24576   // A 16KB + B 8KB per stage
__global__ __launch_bounds__(256) void gemm_kv_p(const float* __restrict__ bias,
                                                 __half* __restrict__ C) {
    extern __shared__ __align__(16) char sm[];
    const uint32_t sb = smem_u32(sm);
    const int t = threadIdx.x, w = t >> 5, lane = t & 31;
    const int m0 = blockIdx.y * 128, n0 = blockIdx.x * 64;
    const int mw_ = (w >> 1) * 32, nw_ = (w & 1) * 32;
    const int qr = lane >> 2, tg = lane & 3;
    const int aL4 = (lane >> 4) & 1, bL3 = (lane >> 3) & 1;
    const int ar = mw_ + (lane & 7) + (lane & 8), ar7 = ar & 7;
    const int br = nw_ + (lane & 7) + aL4 * 8, br7 = br & 7;
    const int pr = t >> 3, pch = t & 7;
#pragma unroll
    for (int pf = 0; pf < 2; pf++) {
        uint32_t base = sb + pf * KV_STG;
#pragma unroll
        for (int i = 0; i < 4; i++) {   // A: 128 rows, zfill past Spad
            int r = pr + i * 32;
            int grow = m0 + r;
            int ok = grow < Spad;
            const __half* src = g_emb_h + (size_t)(ok ? grow : 0) * 256 + pf * 64 + pch * 8;
            cp_async16z(base + toff(r, pch), src, ok);
        }
#pragma unroll
        for (int i = 0; i < 2; i++) {   // B: 64 weight rows
            int r = pr + i * 32;
            cp_async16(base + 16384 + toff(r, pch),
                       g_wkv_h + (n0 + r) * 256 + pf * 64 + pch * 8);
        }
        CP_COMMIT();
    }
    float acc[2][4][4] = {};
    for (int k0 = 0; k0 < 4; k0++) {
        const uint32_t ab = sb + (k0 % 3) * KV_STG, bb_ = ab + 16384;
        CP_WAIT1();
        __syncthreads();
        {
            int kp = k0 + 2;
            if (kp < 4) {
                uint32_t base = sb + (kp % 3) * KV_STG;
#pragma unroll
                for (int i = 0; i < 4; i++) {
                    int r = pr + i * 32;
                    int grow = m0 + r;
                    int ok = grow < Spad;
                    const __half* src = g_emb_h + (size_t)(ok ? grow : 0) * 256 + kp * 64 + pch * 8;
                    cp_async16z(base + toff(r, pch), src, ok);
                }
#pragma unroll
                for (int i = 0; i < 2; i++) {
                    int r = pr + i * 32;
                    cp_async16(base + 16384 + toff(r, pch),
                               g_wkv_h + (n0 + r) * 256 + kp * 64 + pch * 8);
                }
            }
            CP_COMMIT();
        }
#pragma unroll
        for (int kk = 0; kk < 64; kk += 16) {
            int c8 = kk >> 3;
            uint32_t a0, a1, a2, a3, e0, e1, e2, e3;
            uint32_t b0, b1, b2, b3, c0, c1, c2, c3;
            uint32_t axo = ((c8 + aL4) ^ ar7) << 4;
            ldsm_x4(a0, a1, a2, a3, ab + ar * 128 + axo);
            ldsm_x4(e0, e1, e2, e3, ab + (ar + 16) * 128 + axo);
            ldsm_x4(b0, b1, b2, b3, bb_ + br * 128 + (((c8 + bL3) ^ br7) << 4));
            ldsm_x4(c0, c1, c2, c3, bb_ + (br + 16) * 128 + (((c8 + bL3) ^ br7) << 4));
            hmma(acc[0][0], a0, a1, a2, a3, b0, b1);
            hmma(acc[0][1], a0, a1, a2, a3, b2, b3);
            hmma(acc[0][2], a0, a1, a2, a3, c0, c1);
            hmma(acc[0][3], a0, a1, a2, a3, c2, c3);
            hmma(acc[1][0], e0, e1, e2, e3, b0, b1);
            hmma(acc[1][1], e0, e1, e2, e3, b2, b3);
            hmma(acc[1][2], e0, e1, e2, e3, c0, c1);
            hmma(acc[1][3], e0, e1, e2, e3, c2, c3);
        }
    }
#pragma unroll
    for (int rh = 0; rh < 2; rh++) {
        const int r0 = m0 + mw_ + rh * 16 + qr, r1 = r0 + 8;
#pragma unroll
        for (int nt = 0; nt < 4; nt++) {
            int col = n0 + nw_ + nt * 8 + tg * 2;
            float bx = bias[col], by = bias[col + 1];
            if (r0 < Spad)
                *(__half2*)(C + (size_t)r0 * 512 + col) =
                    __floats2half2_rn(acc[rh][nt][0] + bx, acc[rh][nt][1] + by);
            if (r1 < Spad)
                *(__half2*)(C + (size_t)r1 * 512 + col) =
                    __floats2half2_rn(acc[rh][nt][2] + bx, acc[rh][nt][3] + by);
        }
    }
}

// ---------------- v_mean (2-stage, deterministic, 800 blocks, 5-way ILP) ---------
__global__ void vmean1_kernel() {
    int c = blockIdx.x, d = threadIdx.x;
    float s[5] = {};
#pragma unroll
    for (int i = 0; i < 25; i += 5) {
#pragma unroll
        for (int j = 0; j < 5; j++)
            s[j] += __half2float(g_kv[(size_t)(c * 25 + i + j) * 512 + 256 + d]);
    }
    g_vpart[c * Dsz + d] = ((s[0] + s[1]) + (s[2] + s[3])) + s[4];
}
__global__ void vmean2_kernel() {
    int d = threadIdx.x;
    float s = 0.f;
    for (int c = 0; c < 800; c++) s += g_vpart[c * Dsz + d];
    g_vmean[d] = s * (1.0f / (float)Ssz);
}

// ---------------- split-S attention: fp16 mma (f16-accum QK), register-P ---------
#define A_Q   0
#define A_K   8192
#define A_V   32768
#define A_CT  57344
#define A_LS  73728
#define SM_ATT 74240
#define ONES2 0x3C003C00u

__global__ __launch_bounds__(256, 2) void attn_h2() {
    extern __shared__ __align__(16) char sm[];
    const uint32_t sb = smem_u32(sm);
    const uint32_t qb = sb + A_Q;
    float* ctxs = (float*)(sm + A_CT);
    float* lsm  = (float*)(sm + A_LS);
    const int t = threadIdx.x, w = t >> 5, lane = t & 31;
    const int c = blockIdx.x, bt = blockIdx.y, h = blockIdx.z;
    const int mw_ = (w >> 1) * 16, sh = w & 1;
    const int qr = lane >> 2, tg = lane & 3;
    const int aL4 = (lane >> 4) & 1, bL3 = (lane >> 3) & 1;
    const int ar = mw_ + (lane & 7) + (lane & 8), ar7 = ar & 7;
    const int br = sh * 32 + (lane & 7) + aL4 * 8, br7 = br & 7;
    const int vl7 = lane & 7;
    const int r0 = mw_ + qr, r1 = r0 + 8;

    { // Q tile: fp32 -> half, scale = (1/8)*log2(e)
        const float QS = 0.125f * 1.44269504f;
        char* qc = sm + A_Q;
#pragma unroll
        for (int i = 0; i < 2; i++) {
            int idx = t + i * 256;
            int r = idx >> 3, ch = idx & 7;
            const float* qp = g_q + (size_t)(bt * 64 + r) * 256 + h * 64 + ch * 8;
            float4 x = *(const float4*)qp, y = *(const float4*)(qp + 4);
            *(uint4*)(qc + toff(r, ch)) =
                make_uint4(h2pack(x.x * QS, x.y * QS), h2pack(x.z * QS, x.w * QS),
                           h2pack(y.x * QS, y.y * QS), h2pack(y.z * QS, y.w * QS));
        }
    }
    const int t0 = (TTOT * c) / NCH, t1 = (TTOT * (c + 1)) / NCH;
    const int pr = t >> 3, pch = t & 7;
#pragma unroll
    for (int pf = 0; pf < 2; pf++) {
        int ts = t0 + pf;
        if (ts < t1) {
            uint32_t kd = sb + A_K + pf * 8192, vd = sb + A_V + pf * 8192;
#pragma unroll
            for (int i = 0; i < 2; i++) {
                int r = pr + i * 32;
                const __half* kp = g_kv + (size_t)(ts * 64 + r) * 512 + h * 64 + pch * 8;
                cp_async16(kd + toff(r, pch), kp);
                cp_async16(vd + toff(r, pch), kp + 256);
            }
        }
        CP_COMMIT();
    }
    __syncthreads();          // Q tile visible
    uint32_t qa[4][4];
#pragma unroll
    for (int kk4 = 0; kk4 < 4; kk4++)
        ldsm_x4(qa[kk4][0], qa[kk4][1], qa[kk4][2], qa[kk4][3],
                qb + ar * 128 + ((((kk4 * 2) + aL4) ^ ar7) << 4));

    float ctx[8][4] = {};
    float lacc[4] = {};

    for (int ts = t0; ts < t1; ts++) {
        const int st = (ts - t0) % 3;
        const uint32_t kb = sb + A_K + st * 8192;
        const uint32_t vb = sb + A_V + st * 8192;
        CP_WAIT1();
        __syncthreads();
        { // prefetch ts+2
            int tp = ts + 2;
            if (tp < t1) {
                int sp = (ts - t0 + 2) % 3;
                uint32_t kd = sb + A_K + sp * 8192, vd = sb + A_V + sp * 8192;
#pragma unroll
                for (int i = 0; i < 2; i++) {
                    int r = pr + i * 32;
                    const __half* kp = g_kv + (size_t)(tp * 64 + r) * 512 + h * 64 + pch * 8;
                    cp_async16(kd + toff(r, pch), kp);
                    cp_async16(vd + toff(r, pch), kp + 256);
                }
            }
            CP_COMMIT();
        }
        unsigned mwr0 = g_maskT[(size_t)(2 * ts + sh) * Bq + bt * 64 + r0];
        unsigned mwr1 = g_maskT[(size_t)(2 * ts + sh) * Bq + bt * 64 + r1];
        // ---- scores(log2) = Q' @ K^T, fp16 accumulators (half2 fragments) ----
        uint32_t scf2[4][2] = {};
#pragma unroll
        for (int kk = 0; kk < 64; kk += 16) {
            int c8 = kk >> 3, kq = kk >> 4;
            uint32_t b0, b1, b2, b3, c0, c1, c2, c3;
            ldsm_x4(b0, b1, b2, b3, kb + br * 128 + (((c8 + bL3) ^ br7) << 4));
            hmma_h16(scf2[0], qa[kq][0], qa[kq][1], qa[kq][2], qa[kq][3], b0, b1);
            hmma_h16(scf2[1], qa[kq][0], qa[kq][1], qa[kq][2], qa[kq][3], b2, b3);
            ldsm_x4(c0, c1, c2, c3, kb + (br + 16) * 128 + (((c8 + bL3) ^ br7) << 4));
            hmma_h16(scf2[2], qa[kq][0], qa[kq][1], qa[kq][2], qa[kq][3], c0, c1);
            hmma_h16(scf2[3], qa[kq][0], qa[kq][1], qa[kq][2], qa[kq][3], c2, c3);
        }
        // ---- p = 2^score via ex2.f16x2 (direct on fragments), mask by AND ----
        uint32_t pa[2][4];
#pragma unroll
        for (int ks2 = 0; ks2 < 2; ks2++) {
#pragma unroll
            for (int q2 = 0; q2 < 2; q2++) {
                int nt = 2 * ks2 + q2;
                int bp = nt * 8 + tg * 2;
                uint32_t am0 = (((mwr0 >> bp) & 1u) ? 0x0000FFFFu : 0u) |
                               (((mwr0 >> (bp + 1)) & 1u) ? 0xFFFF0000u : 0u);
                uint32_t am1 = (((mwr1 >> bp) & 1u) ? 0x0000FFFFu : 0u) |
                               (((mwr1 >> (bp + 1)) & 1u) ? 0xFFFF0000u : 0u);
                pa[ks2][2 * q2]     = ex2h2(scf2[nt][0]) & am0;
                pa[ks2][2 * q2 + 1] = ex2h2(scf2[nt][1]) & am1;
            }
            hmma(lacc, pa[ks2][0], pa[ks2][1], pa[ks2][2], pa[ks2][3], ONES2, ONES2);
        }
#pragma unroll
        for (int ks2 = 0; ks2 < 2; ks2++) {
            int vrow = sh * 32 + ks2 * 16 + vl7 + bL3 * 8;
            uint32_t A0 = pa[ks2][0], A1 = pa[ks2][1], A2 = pa[ks2][2], A3 = pa[ks2][3];
#pragma unroll
            for (int j = 0; j < 4; j++) {
                uint32_t b0, b1, b2, b3;
                ldsm_x4_t(b0, b1, b2, b3, vb + vrow * 128 + ((((j << 1) + aL4) ^ vl7) << 4));
                hmma(ctx[2 * j],     A0, A1, A2, A3, b0, b1);
                hmma(ctx[2 * j + 1], A0, A1, A2, A3, b2, b3);
            }
        }
    }
    if (sh == 1) {
#pragma unroll
        for (int nc = 0; nc < 8; nc++) {
            *(float2*)&ctxs[r0 * 64 + nc * 8 + tg * 2] = make_float2(ctx[nc][0], ctx[nc][1]);
            *(float2*)&ctxs[r1 * 64 + nc * 8 + tg * 2] = make_float2(ctx[nc][2], ctx[nc][3]);
        }
    }
    if (tg == 0) {
        lsm[sh * 64 + r0] = lacc[0];
        lsm[sh * 64 + r1] = lacc[2];
    }
    __syncthreads();
    if (sh == 0) {
        size_t base = ((size_t)c * Bq + bt * 64) * Dsz + (size_t)h * 64;
#pragma unroll
        for (int nc = 0; nc < 8; nc++) {
            int col = nc * 8 + tg * 2;
            float2 o0 = *(float2*)&ctxs[r0 * 64 + col];
            float2 o1 = *(float2*)&ctxs[r1 * 64 + col];
            *(float2*)(g_part + base + (size_t)r0 * Dsz + col) =
                make_float2(ctx[nc][0] + o0.x, ctx[nc][1] + o0.y);
            *(float2*)(g_part + base + (size_t)r1 * Dsz + col) =
                make_float2(ctx[nc][2] + o1.x, ctx[nc][3] + o1.y);
        }
    }
    if (t < 64)
        g_partl[((size_t)c * Bq + bt * 64 + t) * Hh + h] = lsm[t] + lsm[64 + t];
}

// ---------------- merge partials, normalize (half ctx out) -----------------------
__global__ void reduce_ctx_kernel() {
    int b = blockIdx.x, d = threadIdx.x;
    int h = d >> 6;
    float l = 0.f, s = 0.f;
    for (int c = 0; c < NCH; c++) {
        l += g_partl[((size_t)c * Bq + b) * Hh + h];
        s += g_part[((size_t)c * Bq + b) * Dsz + d];
    }
    float v = (l > 0.f) ? (s / l) : g_vmean[d];
    g_ctx_h[b * Dsz + d] = __float2half_rn(v);
}

// ---------------- launch ---------------------------------------------------------
extern "C" void kernel_launch(void* const* d_in, const int* in_sizes, int n_in,
                              void* d_out, int out_size) {
    const int*   act   = (const int*)d_in[0];
    const float* nc    = (const float*)d_in[1];
    const float* emb   = (const float*)d_in[2];
    const float* w_in  = (const float*)d_in[3];
    const float* b_in  = (const float*)d_in[4];
    const float* w_out = (const float*)d_in[5];
    const float* b_out = (const float*)d_in[6];
    float* out = (float*)d_out;
    (void)in_sizes; (void)n_in; (void)out_size;

    void *p_kv = 0, *p_q = 0;
    void *p_nc = 0, *p_wq = 0, *p_wo = 0, *p_ctx = 0;
    cudaGetSymbolAddress(&p_kv, g_kv);
    cudaGetSymbolAddress(&p_q, g_q);
    cudaGetSymbolAddress(&p_nc, g_nc_h);
    cudaGetSymbolAddress(&p_wq, g_wq_h);
    cudaGetSymbolAddress(&p_wo, g_wo_h);
    cudaGetSymbolAddress(&p_ctx, g_ctx_h);

    cudaFuncSetAttribute(attn_h2, cudaFuncAttributeMaxDynamicSharedMemorySize, SM_ATT);
    cudaFuncSetAttribute(gemm_kv_p, cudaFuncAttributeMaxDynamicSharedMemorySize, 3 * KV_STG);

    pack_mask_kernel<<<Bq, 256>>>(act);
    conv_half<<<CROWS / 4, 256>>>(emb, w_in, nc, w_out);
    gemm_kv_p<<<dim3(8, 157), 256, 3 * KV_STG>>>(b_in + 256, (__half*)p_kv);
    gemm_h<<<dim3(4, 32), 256>>>((const __half*)p_nc, (const __half*)p_wq,
                                 b_in, (float*)p_q);
    vmean1_kernel<<<800, 256>>>();
    vmean2_kernel<<<1, 256>>>();
    attn_h2<<<dim3(NCH, Bq / 64, Hh), 256, SM_ATT>>>();
    reduce_ctx_kernel<<<Bq, 256>>>();
    gemm_h<<<dim3(4, 32), 256>>>((const __half*)p_ctx, (const __half*)p_wo,
                                 b_out, out);
}

// round 15
// speedup vs baseline: 1.0943x; 1.0118x over previous
#include <cuda_runtime.h>
#include <cuda_fp16.h>
#include <cstdint>

#define Bq   1024
#define Ssz  20000
#define Spad 20032          // 64 * 313
#define Dsz  256
#define Hh   4
#define SW2  626            // mask words per batch row incl. padded word
#define NCH  9              // split-S chunks
#define TTOT 313            // 64-row s-tiles total

// ---------------- scratch (static device globals; no allocation) ----------------
__device__ float    g_q[Bq * Dsz];
__device__ __half   g_emb_h[(size_t)Spad * 256];         // half emb, zero-padded
__device__ __half   g_wkv_h[512 * 256];                  // half KV weight rows
__device__ __half   g_nc_h[Bq * 256];                    // half neural_context
__device__ __half   g_wq_h[256 * 256];                   // half Q weight rows
__device__ __half   g_wo_h[256 * 256];                   // half out-proj weights
__device__ __half   g_ctx_h[Bq * Dsz];                   // half ctx (out-proj A)
__device__ __half   g_kv[(size_t)Spad * 512];            // [s][0:256]=k, [256:512]=v
__device__ unsigned g_maskT[SW2 * Bq];                   // word-major: [w][b]
__device__ float    g_part[(size_t)NCH * Bq * Dsz];      // [c][b][h*64+d]
__device__ float    g_partl[NCH * Bq * Hh];
__device__ float    g_vpart[800 * Dsz];
__device__ float    g_vmean[Dsz];

// ---------------- helpers --------------------------------------------------------
__device__ __forceinline__ uint32_t smem_u32(const void* p) {
    uint32_t a;
    asm("{ .reg .u64 t; cvta.to.shared.u64 t, %1; cvt.u32.u64 %0, t; }" : "=r"(a) : "l"(p));
    return a;
}
__device__ __forceinline__ uint32_t h2pack(float a, float b) {
    __half2 h = __floats2half2_rn(a, b);
    return *reinterpret_cast<uint32_t*>(&h);
}
__device__ __forceinline__ uint32_t ex2h2(uint32_t x) {
    uint32_t r;
    asm("ex2.approx.f16x2 %0, %1;" : "=r"(r) : "r"(x));
    return r;
}
// swizzled byte offset inside a 64-col (128B-row) half tile; ch = 8-half chunk
__device__ __forceinline__ int toff(int r, int ch) {
    return r * 128 + ((ch ^ (r & 7)) << 4);
}
__device__ __forceinline__ void ldsm_x4(uint32_t& r0, uint32_t& r1, uint32_t& r2,
                                        uint32_t& r3, uint32_t addr) {
    asm volatile("ldmatrix.sync.aligned.m8n8.x4.shared.b16 {%0,%1,%2,%3}, [%4];"
                 : "=r"(r0), "=r"(r1), "=r"(r2), "=r"(r3) : "r"(addr));
}
__device__ __forceinline__ void ldsm_x4_t(uint32_t& r0, uint32_t& r1, uint32_t& r2,
                                          uint32_t& r3, uint32_t addr) {
    asm volatile("ldmatrix.sync.aligned.m8n8.x4.trans.shared.b16 {%0,%1,%2,%3}, [%4];"
                 : "=r"(r0), "=r"(r1), "=r"(r2), "=r"(r3) : "r"(addr));
}
__device__ __forceinline__ void hmma(float* d, uint32_t a0, uint32_t a1, uint32_t a2,
                                     uint32_t a3, uint32_t b0, uint32_t b1) {
    asm volatile(
        "mma.sync.aligned.m16n8k16.row.col.f32.f16.f16.f32 "
        "{%0,%1,%2,%3},{%4,%5,%6,%7},{%8,%9},{%0,%1,%2,%3};"
        : "+f"(d[0]), "+f"(d[1]), "+f"(d[2]), "+f"(d[3])
        : "r"(a0), "r"(a1), "r"(a2), "r"(a3), "r"(b0), "r"(b1));
}
// f16-accumulator variant: D/C are 2 regs; d[0]=(r0,c..c+1) half2, d[1]=(r1,...)
__device__ __forceinline__ void hmma_h16(uint32_t* d, uint32_t a0, uint32_t a1,
                                         uint32_t a2, uint32_t a3,
                                         uint32_t b0, uint32_t b1) {
    asm volatile(
        "mma.sync.aligned.m16n8k16.row.col.f16.f16.f16.f16 "
        "{%0,%1},{%2,%3,%4,%5},{%6,%7},{%0,%1};"
        : "+r"(d[0]), "+r"(d[1])
        : "r"(a0), "r"(a1), "r"(a2), "r"(a3), "r"(b0), "r"(b1));
}
__device__ __forceinline__ void cp_async16(uint32_t dst, const void* src) {
    asm volatile("cp.async.cg.shared.global [%0], [%1], 16;" :: "r"(dst), "l"(src) : "memory");
}
// zero-fill variant: when pred==0, writes 16 zero bytes without reading src
__device__ __forceinline__ void cp_async16z(uint32_t dst, const void* src, int ok) {
    asm volatile("cp.async.cg.shared.global [%0], [%1], 16, %2;"
                 :: "r"(dst), "l"(src), "r"(ok ? 16 : 0) : "memory");
}
#define CP_COMMIT() asm volatile("cp.async.commit_group;" ::: "memory")
#define CP_WAIT1()  asm volatile("cp.async.wait_group 1;" ::: "memory")
#define CP_WAIT0()  asm volatile("cp.async.wait_group 0;" ::: "memory")
#define BAR_HALF(id) asm volatile("bar.sync %0, 128;" :: "r"(id) : "memory")

// ---------------- mask bit-packing: int4 loads + nibble assembly -----------------
__global__ void pack_mask_kernel(const int* __restrict__ act) {
    __shared__ unsigned char nib[256];
    const int b = blockIdx.x, t = threadIdx.x;
    const int* row = act + (size_t)b * Ssz;
    for (int it = 0; it < 20; it++) {
        int s = it * 1024 + t * 4;
        unsigned n = 0;
        if (s + 3 < Ssz) {
            int4 a = *(const int4*)(row + s);
            n = (unsigned)(a.x > 0) | ((unsigned)(a.y > 0) << 1) |
                ((unsigned)(a.z > 0) << 2) | ((unsigned)(a.w > 0) << 3);
        } else {
#pragma unroll
            for (int j = 0; j < 4; j++) {
                int ss = s + j;
                if (ss < Ssz && row[ss] > 0) n |= 1u << j;
            }
        }
        nib[t] = (unsigned char)n;
        __syncthreads();
        if (t < 32) {
            int w = it * 32 + t;
            if (w < SW2) {
                uint2 v = *(const uint2*)(nib + t * 8);
                unsigned lo = v.x, hi = v.y;
                unsigned word = (lo & 0xFu) | (((lo >> 8) & 0xFu) << 4) |
                                (((lo >> 16) & 0xFu) << 8) | (((lo >> 24) & 0xFu) << 12) |
                                ((hi & 0xFu) << 16) | (((hi >> 8) & 0xFu) << 20) |
                                (((hi >> 16) & 0xFu) << 24) | (((hi >> 24) & 0xFu) << 28);
                g_maskT[w * Bq + b] = word;
            }
        }
        __syncthreads();
    }
}

// ---------------- fp32 -> fp16 pre-conversion ------------------------------------
#define CROWS (Spad + 512 + Bq + 256 + 256)
__global__ void conv_half(const float* __restrict__ emb, const float* __restrict__ w_in,
                          const float* __restrict__ nc, const float* __restrict__ w_out) {
    int idx = blockIdx.x * 256 + threadIdx.x;
    int r = idx >> 6, c = (idx & 63) * 4;
    if (r < Spad) {
        float4 v = make_float4(0.f, 0.f, 0.f, 0.f);
        if (r < Ssz) v = *(const float4*)(emb + (size_t)r * 256 + c);
        *(uint2*)(g_emb_h + (size_t)r * 256 + c) = make_uint2(h2pack(v.x, v.y), h2pack(v.z, v.w));
    } else if (r < Spad + 512) {
        int rw = r - Spad;
        float4 v = *(const float4*)(w_in + (size_t)(256 + rw) * 256 + c);
        *(uint2*)(g_wkv_h + rw * 256 + c) = make_uint2(h2pack(v.x, v.y), h2pack(v.z, v.w));
    } else if (r < Spad + 512 + Bq) {
        int rn = r - Spad - 512;
        float4 v = *(const float4*)(nc + (size_t)rn * 256 + c);
        *(uint2*)(g_nc_h + rn * 256 + c) = make_uint2(h2pack(v.x, v.y), h2pack(v.z, v.w));
    } else if (r < Spad + 512 + Bq + 256) {
        int rw = r - Spad - 512 - Bq;
        float4 v = *(const float4*)(w_in + (size_t)rw * 256 + c);
        *(uint2*)(g_wq_h + rw * 256 + c) = make_uint2(h2pack(v.x, v.y), h2pack(v.z, v.w));
    } else if (r < CROWS) {
        int rw = r - Spad - 512 - Bq - 256;
        float4 v = *(const float4*)(w_out + (size_t)rw * 256 + c);
        *(uint2*)(g_wo_h + rw * 256 + c) = make_uint2(h2pack(v.x, v.y), h2pack(v.z, v.w));
    }
}

// ---------------- fp16 GEMM, fp32 out: single-shot M32xN64, K=256 resident -------
__global__ __launch_bounds__(256) void gemm_h(const __half* __restrict__ Ah,
                                              const __half* __restrict__ Bh,
                                              const float* __restrict__ bias,
                                              float* __restrict__ C) {
    __shared__ __align__(16) char sm[49152];
    const uint32_t sb = smem_u32(sm);
    const int t = threadIdx.x, w = t >> 5, lane = t & 31;
    const int m0 = blockIdx.y * 32, n0 = blockIdx.x * 64;
    const int mw_ = (w >> 2) * 16, nw_ = (w & 3) * 16;
    const int qr = lane >> 2, tg = lane & 3;
    const int aL4 = (lane >> 4) & 1, bL3 = (lane >> 3) & 1;
    const int ar = mw_ + (lane & 7) + (lane & 8), ar7 = ar & 7;
    const int br = nw_ + (lane & 7) + aL4 * 8, br7 = br & 7;
    const int pr = t >> 3, pch = t & 7;
#pragma unroll
    for (int cc = 0; cc < 4; cc++) {
        cp_async16(sb + cc * 4096 + toff(pr, pch),
                   Ah + (size_t)(m0 + pr) * 256 + cc * 64 + pch * 8);
#pragma unroll
        for (int i = 0; i < 2; i++) {
            int r = pr + i * 32;
            cp_async16(sb + 16384 + cc * 8192 + toff(r, pch),
                       Bh + (n0 + r) * 256 + cc * 64 + pch * 8);
        }
    }
    CP_COMMIT();
    CP_WAIT0();
    __syncthreads();
    float acc[2][4] = {};
#pragma unroll
    for (int kk = 0; kk < 256; kk += 16) {
        int cc = kk >> 6, c8 = (kk & 63) >> 3;
        uint32_t a0, a1, a2, a3, b0, b1, b2, b3;
        ldsm_x4(a0, a1, a2, a3, sb + cc * 4096 + ar * 128 + (((c8 + aL4) ^ ar7) << 4));
        ldsm_x4(b0, b1, b2, b3, sb + 16384 + cc * 8192 + br * 128 + (((c8 + bL3) ^ br7) << 4));
        hmma(acc[0], a0, a1, a2, a3, b0, b1);
        hmma(acc[1], a0, a1, a2, a3, b2, b3);
    }
    const int r0 = m0 + mw_ + qr, r1 = r0 + 8;
#pragma unroll
    for (int nt = 0; nt < 2; nt++) {
        int col = n0 + nw_ + nt * 8 + tg * 2;
        float bx = bias[col], by = bias[col + 1];
        *(float2*)(C + (size_t)r0 * 256 + col) = make_float2(acc[nt][0] + bx, acc[nt][1] + by);
        *(float2*)(C + (size_t)r1 * 256 + col) = make_float2(acc[nt][2] + bx, acc[nt][3] + by);
    }
}

// ---------------- KV projection: M128xN64 tiles, M32 warp tiles ------------------
#define KV_STG 24576   // A 16KB + B 8KB per stage
__global__ __launch_bounds__(256) void gemm_kv_p(const float* __restrict__ bias,
                                                 __half* __restrict__ C) {
    extern __shared__ __align__(16) char sm[];
    const uint32_t sb = smem_u32(sm);
    const int t = threadIdx.x, w = t >> 5, lane = t & 31;
    const int m0 = blockIdx.y * 128, n0 = blockIdx.x * 64;
    const int mw_ = (w >> 1) * 32, nw_ = (w & 1) * 32;
    const int qr = lane >> 2, tg = lane & 3;
    const int aL4 = (lane >> 4) & 1, bL3 = (lane >> 3) & 1;
    const int ar = mw_ + (lane & 7) + (lane & 8), ar7 = ar & 7;
    const int br = nw_ + (lane & 7) + aL4 * 8, br7 = br & 7;
    const int pr = t >> 3, pch = t & 7;
#pragma unroll
    for (int pf = 0; pf < 2; pf++) {
        uint32_t base = sb + pf * KV_STG;
#pragma unroll
        for (int i = 0; i < 4; i++) {   // A: 128 rows, zfill past Spad
            int r = pr + i * 32;
            int grow = m0 + r;
            int ok = grow < Spad;
            const __half* src = g_emb_h + (size_t)(ok ? grow : 0) * 256 + pf * 64 + pch * 8;
            cp_async16z(base + toff(r, pch), src, ok);
        }
#pragma unroll
        for (int i = 0; i < 2; i++) {   // B: 64 weight rows
            int r = pr + i * 32;
            cp_async16(base + 16384 + toff(r, pch),
                       g_wkv_h + (n0 + r) * 256 + pf * 64 + pch * 8);
        }
        CP_COMMIT();
    }
    float acc[2][4][4] = {};
    for (int k0 = 0; k0 < 4; k0++) {
        const uint32_t ab = sb + (k0 % 3) * KV_STG, bb_ = ab + 16384;
        CP_WAIT1();
        __syncthreads();
        {
            int kp = k0 + 2;
            if (kp < 4) {
                uint32_t base = sb + (kp % 3) * KV_STG;
#pragma unroll
                for (int i = 0; i < 4; i++) {
                    int r = pr + i * 32;
                    int grow = m0 + r;
                    int ok = grow < Spad;
                    const __half* src = g_emb_h + (size_t)(ok ? grow : 0) * 256 + kp * 64 + pch * 8;
                    cp_async16z(base + toff(r, pch), src, ok);
                }
#pragma unroll
                for (int i = 0; i < 2; i++) {
                    int r = pr + i * 32;
                    cp_async16(base + 16384 + toff(r, pch),
                               g_wkv_h + (n0 + r) * 256 + kp * 64 + pch * 8);
                }
            }
            CP_COMMIT();
        }
#pragma unroll
        for (int kk = 0; kk < 64; kk += 16) {
            int c8 = kk >> 3;
            uint32_t a0, a1, a2, a3, e0, e1, e2, e3;
            uint32_t b0, b1, b2, b3, c0, c1, c2, c3;
            uint32_t axo = ((c8 + aL4) ^ ar7) << 4;
            ldsm_x4(a0, a1, a2, a3, ab + ar * 128 + axo);
            ldsm_x4(e0, e1, e2, e3, ab + (ar + 16) * 128 + axo);
            ldsm_x4(b0, b1, b2, b3, bb_ + br * 128 + (((c8 + bL3) ^ br7) << 4));
            ldsm_x4(c0, c1, c2, c3, bb_ + (br + 16) * 128 + (((c8 + bL3) ^ br7) << 4));
            hmma(acc[0][0], a0, a1, a2, a3, b0, b1);
            hmma(acc[0][1], a0, a1, a2, a3, b2, b3);
            hmma(acc[0][2], a0, a1, a2, a3, c0, c1);
            hmma(acc[0][3], a0, a1, a2, a3, c2, c3);
            hmma(acc[1][0], e0, e1, e2, e3, b0, b1);
            hmma(acc[1][1], e0, e1, e2, e3, b2, b3);
            hmma(acc[1][2], e0, e1, e2, e3, c0, c1);
            hmma(acc[1][3], e0, e1, e2, e3, c2, c3);
        }
    }
#pragma unroll
    for (int rh = 0; rh < 2; rh++) {
        const int r0 = m0 + mw_ + rh * 16 + qr, r1 = r0 + 8;
#pragma unroll
        for (int nt = 0; nt < 4; nt++) {
            int col = n0 + nw_ + nt * 8 + tg * 2;
            float bx = bias[col], by = bias[col + 1];
            if (r0 < Spad)
                *(__half2*)(C + (size_t)r0 * 512 + col) =
                    __floats2half2_rn(acc[rh][nt][0] + bx, acc[rh][nt][1] + by);
            if (r1 < Spad)
                *(__half2*)(C + (size_t)r1 * 512 + col) =
                    __floats2half2_rn(acc[rh][nt][2] + bx, acc[rh][nt][3] + by);
        }
    }
}

// ---------------- v_mean (2-stage, deterministic, 800 blocks, 5-way ILP) ---------
__global__ void vmean1_kernel() {
    int c = blockIdx.x, d = threadIdx.x;
    float s[5] = {};
#pragma unroll
    for (int i = 0; i < 25; i += 5) {
#pragma unroll
        for (int j = 0; j < 5; j++)
            s[j] += __half2float(g_kv[(size_t)(c * 25 + i + j) * 512 + 256 + d]);
    }
    g_vpart[c * Dsz + d] = ((s[0] + s[1]) + (s[2] + s[3])) + s[4];
}
__global__ void vmean2_kernel() {
    int d = threadIdx.x;
    float s = 0.f;
    for (int c = 0; c < 800; c++) s += g_vpart[c * Dsz + d];
    g_vmean[d] = s * (1.0f / (float)Ssz);
}

// ---------------- split-S attention: decoupled s-halves, named barriers ----------
// Each 128-thread half (warps with same sh) owns K/V rows [sh*32, sh*32+32) of
// every stage: loads them, reads them, syncs on its own named barrier. Halves
// run asynchronously through the main loop; full barrier only at the combine.
#define A_Q   0
#define A_K   8192
#define A_V   32768
#define A_CT  57344
#define A_LS  73728
#define SM_ATT 74240
#define ONES2 0x3C003C00u

__global__ __launch_bounds__(256, 2) void attn_h2() {
    extern __shared__ __align__(16) char sm[];
    const uint32_t sb = smem_u32(sm);
    const uint32_t qb = sb + A_Q;
    float* ctxs = (float*)(sm + A_CT);
    float* lsm  = (float*)(sm + A_LS);
    const int t = threadIdx.x, w = t >> 5, lane = t & 31;
    const int c = blockIdx.x, bt = blockIdx.y, h = blockIdx.z;
    const int mw_ = (w >> 1) * 16, sh = w & 1;
    const int qr = lane >> 2, tg = lane & 3;
    const int aL4 = (lane >> 4) & 1, bL3 = (lane >> 3) & 1;
    const int ar = mw_ + (lane & 7) + (lane & 8), ar7 = ar & 7;
    const int br = sh * 32 + (lane & 7) + aL4 * 8, br7 = br & 7;
    const int vl7 = lane & 7;
    const int r0 = mw_ + qr, r1 = r0 + 8;
    // per-half loader map: 128 threads cover rows [sh*32, sh*32+32) x 8 chunks,
    // 2 chunks each for K and V
    const int hidx = (w >> 1) * 32 + lane;          // 0..127 within half
    const int hr = sh * 32 + (hidx >> 2);           // own-half row
    const int hc = (hidx & 3) * 2;                  // chunk pair base

    { // Q tile: fp32 -> half, scale = (1/8)*log2(e)
        const float QS = 0.125f * 1.44269504f;
        char* qc = sm + A_Q;
#pragma unroll
        for (int i = 0; i < 2; i++) {
            int idx = t + i * 256;
            int r = idx >> 3, ch = idx & 7;
            const float* qp = g_q + (size_t)(bt * 64 + r) * 256 + h * 64 + ch * 8;
            float4 x = *(const float4*)qp, y = *(const float4*)(qp + 4);
            *(uint4*)(qc + toff(r, ch)) =
                make_uint4(h2pack(x.x * QS, x.y * QS), h2pack(x.z * QS, x.w * QS),
                           h2pack(y.x * QS, y.y * QS), h2pack(y.z * QS, y.w * QS));
        }
    }
    const int t0 = (TTOT * c) / NCH, t1 = (TTOT * (c + 1)) / NCH;
#pragma unroll
    for (int pf = 0; pf < 2; pf++) {
        int ts = t0 + pf;
        if (ts < t1) {
            uint32_t kd = sb + A_K + pf * 8192, vd = sb + A_V + pf * 8192;
            const __half* kp = g_kv + (size_t)(ts * 64 + hr) * 512 + h * 64 + hc * 8;
            cp_async16(kd + toff(hr, hc),     kp);
            cp_async16(kd + toff(hr, hc + 1), kp + 8);
            cp_async16(vd + toff(hr, hc),     kp + 256);
            cp_async16(vd + toff(hr, hc + 1), kp + 264);
        }
        CP_COMMIT();
    }
    __syncthreads();          // Q tile visible to both halves
    uint32_t qa[4][4];
#pragma unroll
    for (int kk4 = 0; kk4 < 4; kk4++)
        ldsm_x4(qa[kk4][0], qa[kk4][1], qa[kk4][2], qa[kk4][3],
                qb + ar * 128 + ((((kk4 * 2) + aL4) ^ ar7) << 4));

    float ctx[8][4] = {};
    float lacc[4] = {};

    for (int ts = t0; ts < t1; ts++) {
        const int st = (ts - t0) % 3;
        const uint32_t kb = sb + A_K + st * 8192;
        const uint32_t vb = sb + A_V + st * 8192;
        CP_WAIT1();
        BAR_HALF(sh + 1);     // own half only: WAR on this half's stage rows
        { // prefetch ts+2 (own half rows only)
            int tp = ts + 2;
            if (tp < t1) {
                int sp = (ts - t0 + 2) % 3;
                uint32_t kd = sb + A_K + sp * 8192, vd = sb + A_V + sp * 8192;
                const __half* kp = g_kv + (size_t)(tp * 64 + hr) * 512 + h * 64 + hc * 8;
                cp_async16(kd + toff(hr, hc),     kp);
                cp_async16(kd + toff(hr, hc + 1), kp + 8);
                cp_async16(vd + toff(hr, hc),     kp + 256);
                cp_async16(vd + toff(hr, hc + 1), kp + 264);
            }
            CP_COMMIT();
        }
        unsigned mwr0 = g_maskT[(size_t)(2 * ts + sh) * Bq + bt * 64 + r0];
        unsigned mwr1 = g_maskT[(size_t)(2 * ts + sh) * Bq + bt * 64 + r1];
        // ---- scores(log2) = Q' @ K^T, fp16 accumulators (half2 fragments) ----
        uint32_t scf2[4][2] = {};
#pragma unroll
        for (int kk = 0; kk < 64; kk += 16) {
            int c8 = kk >> 3, kq = kk >> 4;
            uint32_t b0, b1, b2, b3, c0, c1, c2, c3;
            ldsm_x4(b0, b1, b2, b3, kb + br * 128 + (((c8 + bL3) ^ br7) << 4));
            hmma_h16(scf2[0], qa[kq][0], qa[kq][1], qa[kq][2], qa[kq][3], b0, b1);
            hmma_h16(scf2[1], qa[kq][0], qa[kq][1], qa[kq][2], qa[kq][3], b2, b3);
            ldsm_x4(c0, c1, c2, c3, kb + (br + 16) * 128 + (((c8 + bL3) ^ br7) << 4));
            hmma_h16(scf2[2], qa[kq][0], qa[kq][1], qa[kq][2], qa[kq][3], c0, c1);
            hmma_h16(scf2[3], qa[kq][0], qa[kq][1], qa[kq][2], qa[kq][3], c2, c3);
        }
        // ---- p = 2^score via ex2.f16x2 (direct on fragments), mask by AND ----
        uint32_t pa[2][4];
#pragma unroll
        for (int ks2 = 0; ks2 < 2; ks2++) {
#pragma unroll
            for (int q2 = 0; q2 < 2; q2++) {
                int nt = 2 * ks2 + q2;
                int bp = nt * 8 + tg * 2;
                uint32_t am0 = (((mwr0 >> bp) & 1u) ? 0x0000FFFFu : 0u) |
                               (((mwr0 >> (bp + 1)) & 1u) ? 0xFFFF0000u : 0u);
                uint32_t am1 = (((mwr1 >> bp) & 1u) ? 0x0000FFFFu : 0u) |
                               (((mwr1 >> (bp + 1)) & 1u) ? 0xFFFF0000u : 0u);
                pa[ks2][2 * q2]     = ex2h2(scf2[nt][0]) & am0;
                pa[ks2][2 * q2 + 1] = ex2h2(scf2[nt][1]) & am1;
            }
            hmma(lacc, pa[ks2][0], pa[ks2][1], pa[ks2][2], pa[ks2][3], ONES2, ONES2);
        }
#pragma unroll
        for (int ks2 = 0; ks2 < 2; ks2++) {
            int vrow = sh * 32 + ks2 * 16 + vl7 + bL3 * 8;
            uint32_t A0 = pa[ks2][0], A1 = pa[ks2][1], A2 = pa[ks2][2], A3 = pa[ks2][3];
#pragma unroll
            for (int j = 0; j < 4; j++) {
                uint32_t b0, b1, b2, b3;
                ldsm_x4_t(b0, b1, b2, b3, vb + vrow * 128 + ((((j << 1) + aL4) ^ vl7) << 4));
                hmma(ctx[2 * j],     A0, A1, A2, A3, b0, b1);
                hmma(ctx[2 * j + 1], A0, A1, A2, A3, b2, b3);
            }
        }
    }
    if (sh == 1) {
#pragma unroll
        for (int nc = 0; nc < 8; nc++) {
            *(float2*)&ctxs[r0 * 64 + nc * 8 + tg * 2] = make_float2(ctx[nc][0], ctx[nc][1]);
            *(float2*)&ctxs[r1 * 64 + nc * 8 + tg * 2] = make_float2(ctx[nc][2], ctx[nc][3]);
        }
    }
    if (tg == 0) {
        lsm[sh * 64 + r0] = lacc[0];
        lsm[sh * 64 + r1] = lacc[2];
    }
    __syncthreads();          // full barrier: cross-half combine
    if (sh == 0) {
        size_t base = ((size_t)c * Bq + bt * 64) * Dsz + (size_t)h * 64;
#pragma unroll
        for (int nc = 0; nc < 8; nc++) {
            int col = nc * 8 + tg * 2;
            float2 o0 = *(float2*)&ctxs[r0 * 64 + col];
            float2 o1 = *(float2*)&ctxs[r1 * 64 + col];
            *(float2*)(g_part + base + (size_t)r0 * Dsz + col) =
                make_float2(ctx[nc][0] + o0.x, ctx[nc][1] + o0.y);
            *(float2*)(g_part + base + (size_t)r1 * Dsz + col) =
                make_float2(ctx[nc][2] + o1.x, ctx[nc][3] + o1.y);
        }
    }
    if (t < 64)
        g_partl[((size_t)c * Bq + bt * 64 + t) * Hh + h] = lsm[t] + lsm[64 + t];
}

// ---------------- merge partials, normalize (half ctx out) -----------------------
__global__ void reduce_ctx_kernel() {
    int b = blockIdx.x, d = threadIdx.x;
    int h = d >> 6;
    float l = 0.f, s = 0.f;
    for (int c = 0; c < NCH; c++) {
        l += g_partl[((size_t)c * Bq + b) * Hh + h];
        s += g_part[((size_t)c * Bq + b) * Dsz + d];
    }
    float v = (l > 0.f) ? (s / l) : g_vmean[d];
    g_ctx_h[b * Dsz + d] = __float2half_rn(v);
}

// ---------------- launch ---------------------------------------------------------
extern "C" void kernel_launch(void* const* d_in, const int* in_sizes, int n_in,
                              void* d_out, int out_size) {
    const int*   act   = (const int*)d_in[0];
    const float* nc    = (const float*)d_in[1];
    const float* emb   = (const float*)d_in[2];
    const float* w_in  = (const float*)d_in[3];
    const float* b_in  = (const float*)d_in[4];
    const float* w_out = (const float*)d_in[5];
    const float* b_out = (const float*)d_in[6];
    float* out = (float*)d_out;
    (void)in_sizes; (void)n_in; (void)out_size;

    void *p_kv = 0, *p_q = 0;
    void *p_nc = 0, *p_wq = 0, *p_wo = 0, *p_ctx = 0;
    cudaGetSymbolAddress(&p_kv, g_kv);
    cudaGetSymbolAddress(&p_q, g_q);
    cudaGetSymbolAddress(&p_nc, g_nc_h);
    cudaGetSymbolAddress(&p_wq, g_wq_h);
    cudaGetSymbolAddress(&p_wo, g_wo_h);
    cudaGetSymbolAddress(&p_ctx, g_ctx_h);

    cudaFuncSetAttribute(attn_h2, cudaFuncAttributeMaxDynamicSharedMemorySize, SM_ATT);
    cudaFuncSetAttribute(gemm_kv_p, cudaFuncAttributeMaxDynamicSharedMemorySize, 3 * KV_STG);

    pack_mask_kernel<<<Bq, 256>>>(act);
    conv_half<<<CROWS / 4, 256>>>(emb, w_in, nc, w_out);
    gemm_kv_p<<<dim3(8, 157), 256, 3 * KV_STG>>>(b_in + 256, (__half*)p_kv);
    gemm_h<<<dim3(4, 32), 256>>>((const __half*)p_nc, (const __half*)p_wq,
                                 b_in, (float*)p_q);
    vmean1_kernel<<<800, 256>>>();
    vmean2_kernel<<<1, 256>>>();
    attn_h2<<<dim3(NCH, Bq / 64, Hh), 256, SM_ATT>>>();
    reduce_ctx_kernel<<<Bq, 256>>>();
    gemm_h<<<dim3(4, 32), 256>>>((const __half*)p_ctx, (const __half*)p_wo,
                                 b_out, out);
}

// round 16
// speedup vs baseline: 1.1096x; 1.0140x over previous
#include <cuda_runtime.h>
#include <cuda_fp16.h>
#include <cstdint>

#define Bq   1024
#define Ssz  20000
#define Spad 20032          // 64 * 313
#define Dsz  256
#define Hh   4
#define SW2  626            // mask words per batch row incl. padded word
#define NCH  9              // split-S chunks
#define TTOT 313            // 64-row s-tiles total

// ---------------- scratch (static device globals; no allocation) ----------------
__device__ float    g_q[Bq * Dsz];
__device__ __half   g_emb_h[(size_t)Spad * 256];         // half emb, zero-padded
__device__ __half   g_wkv_h[512 * 256];                  // half KV weight rows
__device__ __half   g_nc_h[Bq * 256];                    // half neural_context
__device__ __half   g_wq_h[256 * 256];                   // half Q weight rows
__device__ __half   g_wo_h[256 * 256];                   // half out-proj weights
__device__ __half   g_ctx_h[Bq * Dsz];                   // half ctx (out-proj A)
__device__ __half   g_kv[(size_t)Spad * 512];            // [s][0:256]=k, [256:512]=v
__device__ unsigned g_maskT[SW2 * Bq];                   // word-major: [w][b]
__device__ __half   g_part[(size_t)NCH * Bq * Dsz];      // fp16 partials [c][b][h*64+d]
__device__ float    g_partl[NCH * Bq * Hh];
__device__ float    g_vpart[800 * Dsz];
__device__ float    g_vmean[Dsz];

// ---------------- helpers --------------------------------------------------------
__device__ __forceinline__ uint32_t smem_u32(const void* p) {
    uint32_t a;
    asm("{ .reg .u64 t; cvta.to.shared.u64 t, %1; cvt.u32.u64 %0, t; }" : "=r"(a) : "l"(p));
    return a;
}
__device__ __forceinline__ uint32_t h2pack(float a, float b) {
    __half2 h = __floats2half2_rn(a, b);
    return *reinterpret_cast<uint32_t*>(&h);
}
__device__ __forceinline__ uint32_t ex2h2(uint32_t x) {
    uint32_t r;
    asm("ex2.approx.f16x2 %0, %1;" : "=r"(r) : "r"(x));
    return r;
}
// swizzled byte offset inside a 64-col (128B-row) half tile; ch = 8-half chunk
__device__ __forceinline__ int toff(int r, int ch) {
    return r * 128 + ((ch ^ (r & 7)) << 4);
}
__device__ __forceinline__ void ldsm_x4(uint32_t& r0, uint32_t& r1, uint32_t& r2,
                                        uint32_t& r3, uint32_t addr) {
    asm volatile("ldmatrix.sync.aligned.m8n8.x4.shared.b16 {%0,%1,%2,%3}, [%4];"
                 : "=r"(r0), "=r"(r1), "=r"(r2), "=r"(r3) : "r"(addr));
}
__device__ __forceinline__ void ldsm_x4_t(uint32_t& r0, uint32_t& r1, uint32_t& r2,
                                          uint32_t& r3, uint32_t addr) {
    asm volatile("ldmatrix.sync.aligned.m8n8.x4.trans.shared.b16 {%0,%1,%2,%3}, [%4];"
                 : "=r"(r0), "=r"(r1), "=r"(r2), "=r"(r3) : "r"(addr));
}
__device__ __forceinline__ void hmma(float* d, uint32_t a0, uint32_t a1, uint32_t a2,
                                     uint32_t a3, uint32_t b0, uint32_t b1) {
    asm volatile(
        "mma.sync.aligned.m16n8k16.row.col.f32.f16.f16.f32 "
        "{%0,%1,%2,%3},{%4,%5,%6,%7},{%8,%9},{%0,%1,%2,%3};"
        : "+f"(d[0]), "+f"(d[1]), "+f"(d[2]), "+f"(d[3])
        : "r"(a0), "r"(a1), "r"(a2), "r"(a3), "r"(b0), "r"(b1));
}
// f16-accumulator variant: D/C are 2 regs; d[0]=(r0,c..c+1) half2, d[1]=(r1,...)
__device__ __forceinline__ void hmma_h16(uint32_t* d, uint32_t a0, uint32_t a1,
                                         uint32_t a2, uint32_t a3,
                                         uint32_t b0, uint32_t b1) {
    asm volatile(
        "mma.sync.aligned.m16n8k16.row.col.f16.f16.f16.f16 "
        "{%0,%1},{%2,%3,%4,%5},{%6,%7},{%0,%1};"
        : "+r"(d[0]), "+r"(d[1])
        : "r"(a0), "r"(a1), "r"(a2), "r"(a3), "r"(b0), "r"(b1));
}
__device__ __forceinline__ void cp_async16(uint32_t dst, const void* src) {
    asm volatile("cp.async.cg.shared.global [%0], [%1], 16;" :: "r"(dst), "l"(src) : "memory");
}
// zero-fill variant: when pred==0, writes 16 zero bytes without reading src
__device__ __forceinline__ void cp_async16z(uint32_t dst, const void* src, int ok) {
    asm volatile("cp.async.cg.shared.global [%0], [%1], 16, %2;"
                 :: "r"(dst), "l"(src), "r"(ok ? 16 : 0) : "memory");
}
#define CP_COMMIT() asm volatile("cp.async.commit_group;" ::: "memory")
#define CP_WAIT1()  asm volatile("cp.async.wait_group 1;" ::: "memory")
#define CP_WAIT0()  asm volatile("cp.async.wait_group 0;" ::: "memory")
#define BAR_HALF(id) asm volatile("bar.sync %0, 128;" :: "r"(id) : "memory")

// ---------------- mask bit-packing: int4 loads + nibble assembly -----------------
__global__ void pack_mask_kernel(const int* __restrict__ act) {
    __shared__ unsigned char nib[256];
    const int b = blockIdx.x, t = threadIdx.x;
    const int* row = act + (size_t)b * Ssz;
    for (int it = 0; it < 20; it++) {
        int s = it * 1024 + t * 4;
        unsigned n = 0;
        if (s + 3 < Ssz) {
            int4 a = *(const int4*)(row + s);
            n = (unsigned)(a.x > 0) | ((unsigned)(a.y > 0) << 1) |
                ((unsigned)(a.z > 0) << 2) | ((unsigned)(a.w > 0) << 3);
        } else {
#pragma unroll
            for (int j = 0; j < 4; j++) {
                int ss = s + j;
                if (ss < Ssz && row[ss] > 0) n |= 1u << j;
            }
        }
        nib[t] = (unsigned char)n;
        __syncthreads();
        if (t < 32) {
            int w = it * 32 + t;
            if (w < SW2) {
                uint2 v = *(const uint2*)(nib + t * 8);
                unsigned lo = v.x, hi = v.y;
                unsigned word = (lo & 0xFu) | (((lo >> 8) & 0xFu) << 4) |
                                (((lo >> 16) & 0xFu) << 8) | (((lo >> 24) & 0xFu) << 12) |
                                ((hi & 0xFu) << 16) | (((hi >> 8) & 0xFu) << 20) |
                                (((hi >> 16) & 0xFu) << 24) | (((hi >> 24) & 0xFu) << 28);
                g_maskT[w * Bq + b] = word;
            }
        }
        __syncthreads();
    }
}

// ---------------- fp32 -> fp16 pre-conversion ------------------------------------
#define CROWS (Spad + 512 + Bq + 256 + 256)
__global__ void conv_half(const float* __restrict__ emb, const float* __restrict__ w_in,
                          const float* __restrict__ nc, const float* __restrict__ w_out) {
    int idx = blockIdx.x * 256 + threadIdx.x;
    int r = idx >> 6, c = (idx & 63) * 4;
    if (r < Spad) {
        float4 v = make_float4(0.f, 0.f, 0.f, 0.f);
        if (r < Ssz) v = *(const float4*)(emb + (size_t)r * 256 + c);
        *(uint2*)(g_emb_h + (size_t)r * 256 + c) = make_uint2(h2pack(v.x, v.y), h2pack(v.z, v.w));
    } else if (r < Spad + 512) {
        int rw = r - Spad;
        float4 v = *(const float4*)(w_in + (size_t)(256 + rw) * 256 + c);
        *(uint2*)(g_wkv_h + rw * 256 + c) = make_uint2(h2pack(v.x, v.y), h2pack(v.z, v.w));
    } else if (r < Spad + 512 + Bq) {
        int rn = r - Spad - 512;
        float4 v = *(const float4*)(nc + (size_t)rn * 256 + c);
        *(uint2*)(g_nc_h + rn * 256 + c) = make_uint2(h2pack(v.x, v.y), h2pack(v.z, v.w));
    } else if (r < Spad + 512 + Bq + 256) {
        int rw = r - Spad - 512 - Bq;
        float4 v = *(const float4*)(w_in + (size_t)rw * 256 + c);
        *(uint2*)(g_wq_h + rw * 256 + c) = make_uint2(h2pack(v.x, v.y), h2pack(v.z, v.w));
    } else if (r < CROWS) {
        int rw = r - Spad - 512 - Bq - 256;
        float4 v = *(const float4*)(w_out + (size_t)rw * 256 + c);
        *(uint2*)(g_wo_h + rw * 256 + c) = make_uint2(h2pack(v.x, v.y), h2pack(v.z, v.w));
    }
}

// ---------------- fp16 GEMM, fp32 out: single-shot M32xN64, K=256 resident -------
__global__ __launch_bounds__(256) void gemm_h(const __half* __restrict__ Ah,
                                              const __half* __restrict__ Bh,
                                              const float* __restrict__ bias,
                                              float* __restrict__ C) {
    __shared__ __align__(16) char sm[49152];
    const uint32_t sb = smem_u32(sm);
    const int t = threadIdx.x, w = t >> 5, lane = t & 31;
    const int m0 = blockIdx.y * 32, n0 = blockIdx.x * 64;
    const int mw_ = (w >> 2) * 16, nw_ = (w & 3) * 16;
    const int qr = lane >> 2, tg = lane & 3;
    const int aL4 = (lane >> 4) & 1, bL3 = (lane >> 3) & 1;
    const int ar = mw_ + (lane & 7) + (lane & 8), ar7 = ar & 7;
    const int br = nw_ + (lane & 7) + aL4 * 8, br7 = br & 7;
    const int pr = t >> 3, pch = t & 7;
#pragma unroll
    for (int cc = 0; cc < 4; cc++) {
        cp_async16(sb + cc * 4096 + toff(pr, pch),
                   Ah + (size_t)(m0 + pr) * 256 + cc * 64 + pch * 8);
#pragma unroll
        for (int i = 0; i < 2; i++) {
            int r = pr + i * 32;
            cp_async16(sb + 16384 + cc * 8192 + toff(r, pch),
                       Bh + (n0 + r) * 256 + cc * 64 + pch * 8);
        }
    }
    CP_COMMIT();
    CP_WAIT0();
    __syncthreads();
    float acc[2][4] = {};
#pragma unroll
    for (int kk = 0; kk < 256; kk += 16) {
        int cc = kk >> 6, c8 = (kk & 63) >> 3;
        uint32_t a0, a1, a2, a3, b0, b1, b2, b3;
        ldsm_x4(a0, a1, a2, a3, sb + cc * 4096 + ar * 128 + (((c8 + aL4) ^ ar7) << 4));
        ldsm_x4(b0, b1, b2, b3, sb + 16384 + cc * 8192 + br * 128 + (((c8 + bL3) ^ br7) << 4));
        hmma(acc[0], a0, a1, a2, a3, b0, b1);
        hmma(acc[1], a0, a1, a2, a3, b2, b3);
    }
    const int r0 = m0 + mw_ + qr, r1 = r0 + 8;
#pragma unroll
    for (int nt = 0; nt < 2; nt++) {
        int col = n0 + nw_ + nt * 8 + tg * 2;
        float bx = bias[col], by = bias[col + 1];
        *(float2*)(C + (size_t)r0 * 256 + col) = make_float2(acc[nt][0] + bx, acc[nt][1] + by);
        *(float2*)(C + (size_t)r1 * 256 + col) = make_float2(acc[nt][2] + bx, acc[nt][3] + by);
    }
}

// ---------------- KV projection: M128xN64 tiles, M32 warp tiles ------------------
#define KV_STG 24576   // A 16KB + B 8KB per stage
__global__ __launch_bounds__(256) void gemm_kv_p(const float* __restrict__ bias,
                                                 __half* __restrict__ C) {
    extern __shared__ __align__(16) char sm[];
    const uint32_t sb = smem_u32(sm);
    const int t = threadIdx.x, w = t >> 5, lane = t & 31;
    const int m0 = blockIdx.y * 128, n0 = blockIdx.x * 64;
    const int mw_ = (w >> 1) * 32, nw_ = (w & 1) * 32;
    const int qr = lane >> 2, tg = lane & 3;
    const int aL4 = (lane >> 4) & 1, bL3 = (lane >> 3) & 1;
    const int ar = mw_ + (lane & 7) + (lane & 8), ar7 = ar & 7;
    const int br = nw_ + (lane & 7) + aL4 * 8, br7 = br & 7;
    const int pr = t >> 3, pch = t & 7;
#pragma unroll
    for (int pf = 0; pf < 2; pf++) {
        uint32_t base = sb + pf * KV_STG;
#pragma unroll
        for (int i = 0; i < 4; i++) {   // A: 128 rows, zfill past Spad
            int r = pr + i * 32;
            int grow = m0 + r;
            int ok = grow < Spad;
            const __half* src = g_emb_h + (size_t)(ok ? grow : 0) * 256 + pf * 64 + pch * 8;
            cp_async16z(base + toff(r, pch), src, ok);
        }
#pragma unroll
        for (int i = 0; i < 2; i++) {   // B: 64 weight rows
            int r = pr + i * 32;
            cp_async16(base + 16384 + toff(r, pch),
                       g_wkv_h + (n0 + r) * 256 + pf * 64 + pch * 8);
        }
        CP_COMMIT();
    }
    float acc[2][4][4] = {};
    for (int k0 = 0; k0 < 4; k0++) {
        const uint32_t ab = sb + (k0 % 3) * KV_STG, bb_ = ab + 16384;
        CP_WAIT1();
        __syncthreads();
        {
            int kp = k0 + 2;
            if (kp < 4) {
                uint32_t base = sb + (kp % 3) * KV_STG;
#pragma unroll
                for (int i = 0; i < 4; i++) {
                    int r = pr + i * 32;
                    int grow = m0 + r;
                    int ok = grow < Spad;
                    const __half* src = g_emb_h + (size_t)(ok ? grow : 0) * 256 + kp * 64 + pch * 8;
                    cp_async16z(base + toff(r, pch), src, ok);
                }
#pragma unroll
                for (int i = 0; i < 2; i++) {
                    int r = pr + i * 32;
                    cp_async16(base + 16384 + toff(r, pch),
                               g_wkv_h + (n0 + r) * 256 + kp * 64 + pch * 8);
                }
            }
            CP_COMMIT();
        }
#pragma unroll
        for (int kk = 0; kk < 64; kk += 16) {
            int c8 = kk >> 3;
            uint32_t a0, a1, a2, a3, e0, e1, e2, e3;
            uint32_t b0, b1, b2, b3, c0, c1, c2, c3;
            uint32_t axo = ((c8 + aL4) ^ ar7) << 4;
            ldsm_x4(a0, a1, a2, a3, ab + ar * 128 + axo);
            ldsm_x4(e0, e1, e2, e3, ab + (ar + 16) * 128 + axo);
            ldsm_x4(b0, b1, b2, b3, bb_ + br * 128 + (((c8 + bL3) ^ br7) << 4));
            ldsm_x4(c0, c1, c2, c3, bb_ + (br + 16) * 128 + (((c8 + bL3) ^ br7) << 4));
            hmma(acc[0][0], a0, a1, a2, a3, b0, b1);
            hmma(acc[0][1], a0, a1, a2, a3, b2, b3);
            hmma(acc[0][2], a0, a1, a2, a3, c0, c1);
            hmma(acc[0][3], a0, a1, a2, a3, c2, c3);
            hmma(acc[1][0], e0, e1, e2, e3, b0, b1);
            hmma(acc[1][1], e0, e1, e2, e3, b2, b3);
            hmma(acc[1][2], e0, e1, e2, e3, c0, c1);
            hmma(acc[1][3], e0, e1, e2, e3, c2, c3);
        }
    }
#pragma unroll
    for (int rh = 0; rh < 2; rh++) {
        const int r0 = m0 + mw_ + rh * 16 + qr, r1 = r0 + 8;
#pragma unroll
        for (int nt = 0; nt < 4; nt++) {
            int col = n0 + nw_ + nt * 8 + tg * 2;
            float bx = bias[col], by = bias[col + 1];
            if (r0 < Spad)
                *(__half2*)(C + (size_t)r0 * 512 + col) =
                    __floats2half2_rn(acc[rh][nt][0] + bx, acc[rh][nt][1] + by);
            if (r1 < Spad)
                *(__half2*)(C + (size_t)r1 * 512 + col) =
                    __floats2half2_rn(acc[rh][nt][2] + bx, acc[rh][nt][3] + by);
        }
    }
}

// ---------------- v_mean (2-stage, deterministic, 800 blocks, 5-way ILP) ---------
__global__ void vmean1_kernel() {
    int c = blockIdx.x, d = threadIdx.x;
    float s[5] = {};
#pragma unroll
    for (int i = 0; i < 25; i += 5) {
#pragma unroll
        for (int j = 0; j < 5; j++)
            s[j] += __half2float(g_kv[(size_t)(c * 25 + i + j) * 512 + 256 + d]);
    }
    g_vpart[c * Dsz + d] = ((s[0] + s[1]) + (s[2] + s[3])) + s[4];
}
__global__ void vmean2_kernel() {
    int d = threadIdx.x;
    float s = 0.f;
    for (int c = 0; c < 800; c++) s += g_vpart[c * Dsz + d];
    g_vmean[d] = s * (1.0f / (float)Ssz);
}

// ---------------- split-S attention: decoupled s-halves, interleaved exp/PV ------
#define A_Q   0
#define A_K   8192
#define A_V   32768
#define A_CT  57344
#define A_LS  73728
#define SM_ATT 74240
#define ONES2 0x3C003C00u

__global__ __launch_bounds__(256, 2) void attn_h2() {
    extern __shared__ __align__(16) char sm[];
    const uint32_t sb = smem_u32(sm);
    const uint32_t qb = sb + A_Q;
    float* ctxs = (float*)(sm + A_CT);
    float* lsm  = (float*)(sm + A_LS);
    const int t = threadIdx.x, w = t >> 5, lane = t & 31;
    const int c = blockIdx.x, bt = blockIdx.y, h = blockIdx.z;
    const int mw_ = (w >> 1) * 16, sh = w & 1;
    const int qr = lane >> 2, tg = lane & 3;
    const int aL4 = (lane >> 4) & 1, bL3 = (lane >> 3) & 1;
    const int ar = mw_ + (lane & 7) + (lane & 8), ar7 = ar & 7;
    const int br = sh * 32 + (lane & 7) + aL4 * 8, br7 = br & 7;
    const int vl7 = lane & 7;
    const int r0 = mw_ + qr, r1 = r0 + 8;
    const int hidx = (w >> 1) * 32 + lane;          // 0..127 within half
    const int hr = sh * 32 + (hidx >> 2);           // own-half row
    const int hc = (hidx & 3) * 2;                  // chunk pair base

    { // Q tile: fp32 -> half, scale = (1/8)*log2(e)
        const float QS = 0.125f * 1.44269504f;
        char* qc = sm + A_Q;
#pragma unroll
        for (int i = 0; i < 2; i++) {
            int idx = t + i * 256;
            int r = idx >> 3, ch = idx & 7;
            const float* qp = g_q + (size_t)(bt * 64 + r) * 256 + h * 64 + ch * 8;
            float4 x = *(const float4*)qp, y = *(const float4*)(qp + 4);
            *(uint4*)(qc + toff(r, ch)) =
                make_uint4(h2pack(x.x * QS, x.y * QS), h2pack(x.z * QS, x.w * QS),
                           h2pack(y.x * QS, y.y * QS), h2pack(y.z * QS, y.w * QS));
        }
    }
    const int t0 = (TTOT * c) / NCH, t1 = (TTOT * (c + 1)) / NCH;
#pragma unroll
    for (int pf = 0; pf < 2; pf++) {
        int ts = t0 + pf;
        if (ts < t1) {
            uint32_t kd = sb + A_K + pf * 8192, vd = sb + A_V + pf * 8192;
            const __half* kp = g_kv + (size_t)(ts * 64 + hr) * 512 + h * 64 + hc * 8;
            cp_async16(kd + toff(hr, hc),     kp);
            cp_async16(kd + toff(hr, hc + 1), kp + 8);
            cp_async16(vd + toff(hr, hc),     kp + 256);
            cp_async16(vd + toff(hr, hc + 1), kp + 264);
        }
        CP_COMMIT();
    }
    __syncthreads();          // Q tile visible to both halves
    uint32_t qa[4][4];
#pragma unroll
    for (int kk4 = 0; kk4 < 4; kk4++)
        ldsm_x4(qa[kk4][0], qa[kk4][1], qa[kk4][2], qa[kk4][3],
                qb + ar * 128 + ((((kk4 * 2) + aL4) ^ ar7) << 4));

    float ctx[8][4] = {};
    float lacc[4] = {};

    for (int ts = t0; ts < t1; ts++) {
        const int st = (ts - t0) % 3;
        const uint32_t kb = sb + A_K + st * 8192;
        const uint32_t vb = sb + A_V + st * 8192;
        CP_WAIT1();
        BAR_HALF(sh + 1);     // own half only: WAR on this half's stage rows
        { // prefetch ts+2 (own half rows only)
            int tp = ts + 2;
            if (tp < t1) {
                int sp = (ts - t0 + 2) % 3;
                uint32_t kd = sb + A_K + sp * 8192, vd = sb + A_V + sp * 8192;
                const __half* kp = g_kv + (size_t)(tp * 64 + hr) * 512 + h * 64 + hc * 8;
                cp_async16(kd + toff(hr, hc),     kp);
                cp_async16(kd + toff(hr, hc + 1), kp + 8);
                cp_async16(vd + toff(hr, hc),     kp + 256);
                cp_async16(vd + toff(hr, hc + 1), kp + 264);
            }
            CP_COMMIT();
        }
        unsigned mwr0 = g_maskT[(size_t)(2 * ts + sh) * Bq + bt * 64 + r0];
        unsigned mwr1 = g_maskT[(size_t)(2 * ts + sh) * Bq + bt * 64 + r1];
        // ---- scores(log2) = Q' @ K^T, fp16 accumulators (half2 fragments) ----
        uint32_t scf2[4][2] = {};
#pragma unroll
        for (int kk = 0; kk < 64; kk += 16) {
            int c8 = kk >> 3, kq = kk >> 4;
            uint32_t b0, b1, b2, b3, c0, c1, c2, c3;
            ldsm_x4(b0, b1, b2, b3, kb + br * 128 + (((c8 + bL3) ^ br7) << 4));
            hmma_h16(scf2[0], qa[kq][0], qa[kq][1], qa[kq][2], qa[kq][3], b0, b1);
            hmma_h16(scf2[1], qa[kq][0], qa[kq][1], qa[kq][2], qa[kq][3], b2, b3);
            ldsm_x4(c0, c1, c2, c3, kb + (br + 16) * 128 + (((c8 + bL3) ^ br7) << 4));
            hmma_h16(scf2[2], qa[kq][0], qa[kq][1], qa[kq][2], qa[kq][3], c0, c1);
            hmma_h16(scf2[3], qa[kq][0], qa[kq][1], qa[kq][2], qa[kq][3], c2, c3);
        }
        // ---- per ks2 chunk: exp+mask, l-sum, PV (interleaved for issue overlap) --
#pragma unroll
        for (int ks2 = 0; ks2 < 2; ks2++) {
            uint32_t pa[4];
#pragma unroll
            for (int q2 = 0; q2 < 2; q2++) {
                int nt = 2 * ks2 + q2;
                int bp = nt * 8 + tg * 2;
                uint32_t am0 = (((mwr0 >> bp) & 1u) ? 0x0000FFFFu : 0u) |
                               (((mwr0 >> (bp + 1)) & 1u) ? 0xFFFF0000u : 0u);
                uint32_t am1 = (((mwr1 >> bp) & 1u) ? 0x0000FFFFu : 0u) |
                               (((mwr1 >> (bp + 1)) & 1u) ? 0xFFFF0000u : 0u);
                pa[2 * q2]     = ex2h2(scf2[nt][0]) & am0;
                pa[2 * q2 + 1] = ex2h2(scf2[nt][1]) & am1;
            }
            hmma(lacc, pa[0], pa[1], pa[2], pa[3], ONES2, ONES2);
            int vrow = sh * 32 + ks2 * 16 + vl7 + bL3 * 8;
#pragma unroll
            for (int j = 0; j < 4; j++) {
                uint32_t b0, b1, b2, b3;
                ldsm_x4_t(b0, b1, b2, b3, vb + vrow * 128 + ((((j << 1) + aL4) ^ vl7) << 4));
                hmma(ctx[2 * j],     pa[0], pa[1], pa[2], pa[3], b0, b1);
                hmma(ctx[2 * j + 1], pa[0], pa[1], pa[2], pa[3], b2, b3);
            }
        }
    }
    if (sh == 1) {
#pragma unroll
        for (int nc = 0; nc < 8; nc++) {
            *(float2*)&ctxs[r0 * 64 + nc * 8 + tg * 2] = make_float2(ctx[nc][0], ctx[nc][1]);
            *(float2*)&ctxs[r1 * 64 + nc * 8 + tg * 2] = make_float2(ctx[nc][2], ctx[nc][3]);
        }
    }
    if (tg == 0) {
        lsm[sh * 64 + r0] = lacc[0];
        lsm[sh * 64 + r1] = lacc[2];
    }
    __syncthreads();          // full barrier: cross-half combine
    if (sh == 0) {
        size_t base = ((size_t)c * Bq + bt * 64) * Dsz + (size_t)h * 64;
#pragma unroll
        for (int nc = 0; nc < 8; nc++) {
            int col = nc * 8 + tg * 2;
            float2 o0 = *(float2*)&ctxs[r0 * 64 + col];
            float2 o1 = *(float2*)&ctxs[r1 * 64 + col];
            *(uint32_t*)(g_part + base + (size_t)r0 * Dsz + col) =
                h2pack(ctx[nc][0] + o0.x, ctx[nc][1] + o0.y);
            *(uint32_t*)(g_part + base + (size_t)r1 * Dsz + col) =
                h2pack(ctx[nc][2] + o1.x, ctx[nc][3] + o1.y);
        }
    }
    if (t < 64)
        g_partl[((size_t)c * Bq + bt * 64 + t) * Hh + h] = lsm[t] + lsm[64 + t];
}

// ---------------- merge partials (fp16), normalize (half ctx out) ----------------
__global__ void reduce_ctx_kernel() {
    int b = blockIdx.x, d = threadIdx.x;
    int h = d >> 6;
    float l = 0.f, s = 0.f;
    for (int c = 0; c < NCH; c++) {
        l += g_partl[((size_t)c * Bq + b) * Hh + h];
        s += __half2float(g_part[((size_t)c * Bq + b) * Dsz + d]);
    }
    float v = (l > 0.f) ? (s / l) : g_vmean[d];
    g_ctx_h[b * Dsz + d] = __float2half_rn(v);
}

// ---------------- launch ---------------------------------------------------------
extern "C" void kernel_launch(void* const* d_in, const int* in_sizes, int n_in,
                              void* d_out, int out_size) {
    const int*   act   = (const int*)d_in[0];
    const float* nc    = (const float*)d_in[1];
    const float* emb   = (const float*)d_in[2];
    const float* w_in  = (const float*)d_in[3];
    const float* b_in  = (const float*)d_in[4];
    const float* w_out = (const float*)d_in[5];
    const float* b_out = (const float*)d_in[6];
    float* out = (float*)d_out;
    (void)in_sizes; (void)n_in; (void)out_size;

    void *p_kv = 0, *p_q = 0;
    void *p_nc = 0, *p_wq = 0, *p_wo = 0, *p_ctx = 0;
    cudaGetSymbolAddress(&p_kv, g_kv);
    cudaGetSymbolAddress(&p_q, g_q);
    cudaGetSymbolAddress(&p_nc, g_nc_h);
    cudaGetSymbolAddress(&p_wq, g_wq_h);
    cudaGetSymbolAddress(&p_wo, g_wo_h);
    cudaGetSymbolAddress(&p_ctx, g_ctx_h);

    cudaFuncSetAttribute(attn_h2, cudaFuncAttributeMaxDynamicSharedMemorySize, SM_ATT);
    cudaFuncSetAttribute(gemm_kv_p, cudaFuncAttributeMaxDynamicSharedMemorySize, 3 * KV_STG);

    pack_mask_kernel<<<Bq, 256>>>(act);
    conv_half<<<CROWS / 4, 256>>>(emb, w_in, nc, w_out);
    gemm_kv_p<<<dim3(8, 157), 256, 3 * KV_STG>>>(b_in + 256, (__half*)p_kv);
    gemm_h<<<dim3(4, 32), 256>>>((const __half*)p_nc, (const __half*)p_wq,
                                 b_in, (float*)p_q);
    vmean1_kernel<<<800, 256>>>();
    vmean2_kernel<<<1, 256>>>();
    attn_h2<<<dim3(NCH, Bq / 64, Hh), 256, SM_ATT>>>();
    reduce_ctx_kernel<<<Bq, 256>>>();
    gemm_h<<<dim3(4, 32), 256>>>((const __half*)p_ctx, (const __half*)p_wo,
                                 b_out, out);
}